// round 4
// baseline (speedup 1.0000x reference)
#include <cuda_runtime.h>
#include <float.h>
#include <stdint.h>

// Problem constants
#define B_   2
#define D_   64
#define KDIM 67
#define N1_  16384
#define N2_  16384

// Tiling: CTA computes 128(m) x N2 sweep in 64(n) tiles. 8 warps in 4x2.
#define BM 128
#define BN 64
#define NT (N2_/BN)     // 256 tiles
#define KG 26           // k-groups of 8 tf32 slots (208 slots, 201 real)
#define NTH 256

// SMEM layout (bytes)
#define A_OFF  0
#define ABYTES (KG*8*128*4)          // 106496: 208 A-blocks of 128 floats
#define B_OFF  ABYTES
#define BBYTES (KG*4*128*4)          // 53248: 104 B-superblocks per buffer
#define SQ_OFF (B_OFF + 2*BBYTES)
#define SMEM_TOTAL (SQ_OFF + 2*BN*4 + 16)   // ~213.5 KB

__device__ float g_sq2[B_ * N2_];

// ---------------------------------------------------------------------------
__device__ __forceinline__ uint32_t f2tf(float x) {
    uint32_t r; asm("cvt.rna.tf32.f32 %0, %1;" : "=r"(r) : "f"(x)); return r;
}
struct Slot { int k; bool lo; bool valid; };
// B slot map: [0,67)->hi, [67,134)->lo, [134,201)->hi, rest zero
__device__ __forceinline__ Slot decodeB(int s) {
    Slot r; r.valid = s < 201; r.lo = (s >= 67 && s < 134);
    r.k = s < 67 ? s : (s < 134 ? s - 67 : s - 134); return r;
}
// A slot map: [0,67)->hi, [67,134)->hi, [134,201)->lo
__device__ __forceinline__ Slot decodeA(int s) {
    Slot r; r.valid = s < 201; r.lo = (s >= 134 && s < 201);
    r.k = s < 67 ? s : (s < 134 ? s - 67 : s - 134); return r;
}
__device__ __forceinline__ const float* srcPtr(const float* P, const float* X,
                                               int k, int stride) {
    return k < D_ ? P + (size_t)k * stride : X + (size_t)(k - D_) * stride;
}
__device__ __forceinline__ uint32_t pick(float x, bool lo, bool valid) {
    if (!valid) return 0u;
    uint32_t hb = f2tf(x);
    if (!lo) return hb;
    float l = x - __uint_as_float(hb);   // exact residual
    return f2tf(l);
}

#define MMA8(C, A, b0v, b1v)                                              \
  asm volatile("mma.sync.aligned.m16n8k8.row.col.f32.tf32.tf32.f32 "      \
    "{%0,%1,%2,%3}, {%4,%5,%6,%7}, {%8,%9}, {%0,%1,%2,%3};"               \
    : "+f"((C)[0]), "+f"((C)[1]), "+f"((C)[2]), "+f"((C)[3])              \
    : "r"((A).x), "r"((A).y), "r"((A).z), "r"((A).w), "r"(b0v), "r"(b1v))

// ---------------------------------------------------------------------------
__global__ void sq2_kernel(const float* __restrict__ xyz2,
                           const float* __restrict__ points2) {
    int idx = blockIdx.x * blockDim.x + threadIdx.x;
    if (idx >= B_ * N2_) return;
    int b = idx / N2_, j = idx % N2_;
    const float* p = points2 + (size_t)b * D_ * N2_ + j;
    float s = 0.f;
    #pragma unroll
    for (int d = 0; d < D_; d++) { float v = p[(size_t)d * N2_]; s += v * v; }
    const float* x = xyz2 + (size_t)b * 3 * N2_ + j;
    #pragma unroll
    for (int d = 0; d < 3; d++) { float v = x[(size_t)d * N2_]; s += v * v; }
    g_sq2[idx] = s;
}

// ---------------------------------------------------------------------------
// Fused 3xTF32 mma.sync GEMM + streaming argmin.
// Fragment-thread-major SMEM layouts: one LDS.128 per fragment, no conflicts.
// ---------------------------------------------------------------------------
__global__ void __launch_bounds__(NTH, 1)
nn_mma_kernel(const float* __restrict__ xyz1, const float* __restrict__ xyz2,
              const float* __restrict__ points1, const float* __restrict__ points2,
              float* __restrict__ out) {
    extern __shared__ char smem[];
    const int tid  = threadIdx.x;
    const int w    = tid >> 5, lane = tid & 31;
    const int wr   = w >> 1, wc = w & 1;       // 4x2 warp grid
    const int lr   = lane >> 2, lc = lane & 3;
    const int b    = blockIdx.y;
    const int m0   = blockIdx.x * BM;

    const float* P1 = points1 + (size_t)b * D_ * N1_;
    const float* X1 = xyz1    + (size_t)b * 3  * N1_;
    const float* P2 = points2 + (size_t)b * D_ * N2_;
    const float* X2 = xyz2    + (size_t)b * 3  * N2_;
    float* shSq = (float*)(smem + SQ_OFF);

    // ---- A prologue: 208 blocks of 16m x 8k', thread-major frag layout ----
    for (int ab = w; ab < KG * 8; ab += 8) {
        int g = ab >> 3, fA = ab & 7;
        int m1 = m0 + fA * 16 + lr;
        int s0 = g * 8 + lc, s1 = s0 + 4;
        Slot d0 = decodeA(s0), d1 = decodeA(s1);
        float xa = 0, xb = 0, xc = 0, xd = 0;
        if (d0.valid) { const float* p = srcPtr(P1, X1, d0.k, N1_); xa = p[m1]; xb = p[m1 + 8]; }
        if (d1.valid) { const float* p = srcPtr(P1, X1, d1.k, N1_); xc = p[m1]; xd = p[m1 + 8]; }
        uint4 v;
        v.x = pick(xa, d0.lo, d0.valid);   // a0 = (m1,   s0)
        v.y = pick(xb, d0.lo, d0.valid);   // a1 = (m1+8, s0)
        v.z = pick(xc, d1.lo, d1.valid);   // a2 = (m1,   s1)
        v.w = pick(xd, d1.lo, d1.valid);   // a3 = (m1+8, s1)
        *(uint4*)(smem + A_OFF + ((size_t)ab * 128 + lane * 4) * 4) = v;
    }
    // ---- B tile 0 prologue: 104 superblocks (2 n-frags each) ----
    for (int sbi = 0; sbi < 13; sbi++) {
        int sb = sbi * 8 + w;
        int kg = sb >> 2, q = sb & 3;
        int n1 = q * 16 + lr, n2 = n1 + 8;
        int s0 = kg * 8 + lc, s1 = s0 + 4;
        Slot d0 = decodeB(s0), d1 = decodeB(s1);
        float xa = 0, xb = 0, xc = 0, xd = 0;
        if (d0.valid) { const float* p = srcPtr(P2, X2, d0.k, N2_); xa = p[n1]; xc = p[n2]; }
        if (d1.valid) { const float* p = srcPtr(P2, X2, d1.k, N2_); xb = p[n1]; xd = p[n2]; }
        uint4 v;
        v.x = pick(xa, d0.lo, d0.valid);   // frag-even b0 = (s0, n1)
        v.y = pick(xb, d1.lo, d1.valid);   // frag-even b1 = (s1, n1)
        v.z = pick(xc, d0.lo, d0.valid);   // frag-odd  b0 = (s0, n2)
        v.w = pick(xd, d1.lo, d1.valid);   // frag-odd  b1 = (s1, n2)
        *(uint4*)(smem + B_OFF + ((size_t)sb * 128 + lane * 4) * 4) = v;
    }
    if (tid < BN) shSq[tid] = g_sq2[b * N2_ + tid];
    __syncthreads();

    float bestV[4] = {FLT_MAX, FLT_MAX, FLT_MAX, FLT_MAX};
    int   bestI[4] = {0, 0, 0, 0};

    for (int t = 0; t < NT; t++) {
        const int cur = t & 1;
        char* bufC = smem + B_OFF + cur * BBYTES;
        char* bufN = smem + B_OFF + (cur ^ 1) * BBYTES;
        const int sbn = (t + 1 < NT) ? 13 : 0;
        const int n0n = (t + 1) * BN;

        float acc[2][4][4];
        #pragma unroll
        for (int f = 0; f < 2; f++)
            #pragma unroll
            for (int nf = 0; nf < 4; nf++)
                #pragma unroll
                for (int r = 0; r < 4; r++) acc[f][nf][r] = 0.f;

        float px[4]; int psb = -1;

        #pragma unroll 1
        for (int g = 0; g < KG; g++) {
            // STS stage: flush previous superblock (LDG latency hidden 1 iter)
            if (psb >= 0) {
                int kg = psb >> 2;
                int s0 = kg * 8 + lc, s1 = s0 + 4;
                Slot d0 = decodeB(s0), d1 = decodeB(s1);
                uint4 v;
                v.x = pick(px[0], d0.lo, d0.valid);
                v.y = pick(px[1], d1.lo, d1.valid);
                v.z = pick(px[2], d0.lo, d0.valid);
                v.w = pick(px[3], d1.lo, d1.valid);
                *(uint4*)(bufN + ((size_t)psb * 128 + lane * 4) * 4) = v;
                psb = -1;
            }
            // LDG stage for next tile
            if (g < sbn) {
                int sb = g * 8 + w;
                int kg = sb >> 2, q = sb & 3;
                int n1 = n0n + q * 16 + lr, n2 = n1 + 8;
                int s0 = kg * 8 + lc, s1 = s0 + 4;
                Slot d0 = decodeB(s0), d1 = decodeB(s1);
                px[0] = px[1] = px[2] = px[3] = 0.f;
                if (d0.valid) { const float* p = srcPtr(P2, X2, d0.k, N2_); px[0] = __ldg(p + n1); px[2] = __ldg(p + n2); }
                if (d1.valid) { const float* p = srcPtr(P2, X2, d1.k, N2_); px[1] = __ldg(p + n1); px[3] = __ldg(p + n2); }
                psb = sb;
            }
            // Fragments: one LDS.128 each, conflict-free
            uint4 ra0 = *(const uint4*)(smem + A_OFF + ((size_t)(g * 8 + wr * 2 + 0) * 128 + lane * 4) * 4);
            uint4 ra1 = *(const uint4*)(smem + A_OFF + ((size_t)(g * 8 + wr * 2 + 1) * 128 + lane * 4) * 4);
            uint4 rb0 = *(const uint4*)(bufC + ((size_t)(g * 4 + wc * 2 + 0) * 128 + lane * 4) * 4);
            uint4 rb1 = *(const uint4*)(bufC + ((size_t)(g * 4 + wc * 2 + 1) * 128 + lane * 4) * 4);

            MMA8(acc[0][0], ra0, rb0.x, rb0.y);
            MMA8(acc[0][1], ra0, rb0.z, rb0.w);
            MMA8(acc[0][2], ra0, rb1.x, rb1.y);
            MMA8(acc[0][3], ra0, rb1.z, rb1.w);
            MMA8(acc[1][0], ra1, rb0.x, rb0.y);
            MMA8(acc[1][1], ra1, rb0.z, rb0.w);
            MMA8(acc[1][2], ra1, rb1.x, rb1.y);
            MMA8(acc[1][3], ra1, rb1.z, rb1.w);
        }

        // Epilogue: score = |f2|^2 - 2*dot, running argmin (j ascending)
        #pragma unroll
        for (int f = 0; f < 2; f++)
            #pragma unroll
            for (int nf = 0; nf < 4; nf++) {
                int nb = wc * 32 + nf * 8 + 2 * lc;
                float s0 = shSq[cur * BN + nb];
                float s1 = shSq[cur * BN + nb + 1];
                int j0 = t * BN + nb;
                #pragma unroll
                for (int h = 0; h < 2; h++) {
                    int bi = f * 2 + h;
                    float sc0 = fmaf(-2.f, acc[f][nf][h * 2 + 0], s0);
                    float sc1 = fmaf(-2.f, acc[f][nf][h * 2 + 1], s1);
                    if (sc0 < bestV[bi]) { bestV[bi] = sc0; bestI[bi] = j0; }
                    if (sc1 < bestV[bi]) { bestV[bi] = sc1; bestI[bi] = j0 + 1; }
                }
            }
        if (tid < BN && t + 1 < NT)
            shSq[(cur ^ 1) * BN + tid] = g_sq2[b * N2_ + n0n + tid];
        __syncthreads();
    }

    // Lane reduction: candidates for a row live in lanes sharing lr (lc=0..3)
    #pragma unroll
    for (int off = 1; off <= 2; off <<= 1) {
        #pragma unroll
        for (int r = 0; r < 4; r++) {
            float ov = __shfl_xor_sync(0xffffffff, bestV[r], off);
            int   oi = __shfl_xor_sync(0xffffffff, bestI[r], off);
            if (ov < bestV[r] || (ov == bestV[r] && oi < bestI[r])) {
                bestV[r] = ov; bestI[r] = oi;
            }
        }
    }
    __syncthreads();                       // done with A/B smem, reuse it
    float* sv = (float*)smem;              // [128][2]
    int*   si = (int*)(smem + 128 * 2 * 4);
    if (lc == 0) {
        #pragma unroll
        for (int r = 0; r < 4; r++) {
            int row = wr * 32 + (r >> 1) * 16 + lr + (r & 1) * 8;
            sv[row * 2 + wc] = bestV[r];
            si[row * 2 + wc] = bestI[r];
        }
    }
    __syncthreads();

    if (tid < BM) {
        float v0 = sv[tid * 2], v1 = sv[tid * 2 + 1];
        int   i0 = si[tid * 2], i1 = si[tid * 2 + 1];
        int   bi = (v1 < v0 || (v1 == v0 && i1 < i0)) ? i1 : i0;
        int   gi = m0 + tid;
        out[b * N1_ + gi]        = (float)gi;
        out[(B_ + b) * N1_ + gi] = (float)bi;
        float* dir = out + 2 * B_ * N1_;
        #pragma unroll
        for (int d = 0; d < 3; d++)
            dir[((size_t)b * 3 + d) * N1_ + gi] =
                X2[(size_t)d * N2_ + bi] - X1[(size_t)d * N1_ + gi];
    }
}

// ---------------------------------------------------------------------------
extern "C" void kernel_launch(void* const* d_in, const int* in_sizes, int n_in,
                              void* d_out, int out_size) {
    const float* xyz1    = (const float*)d_in[0];
    const float* xyz2    = (const float*)d_in[1];
    const float* points1 = (const float*)d_in[2];
    const float* points2 = (const float*)d_in[3];
    float* out = (float*)d_out;

    sq2_kernel<<<(B_ * N2_ + 255) / 256, 256>>>(xyz2, points2);

    cudaFuncSetAttribute(nn_mma_kernel,
                         cudaFuncAttributeMaxDynamicSharedMemorySize,
                         SMEM_TOTAL);
    dim3 grid(N1_ / BM, B_);
    nn_mma_kernel<<<grid, NTH, SMEM_TOTAL>>>(xyz1, xyz2, points1, points2, out);
}

// round 5
// speedup vs baseline: 3.2495x; 3.2495x over previous
#include <cuda_runtime.h>
#include <float.h>
#include <stdint.h>

// Problem constants
#define B_   2
#define D_   64
#define KDIM 67
#define N1_  16384
#define N2_  16384

#define BM 128
#define BN 64
#define NT (N2_/BN)      // 256
#define MT (N1_/BM)      // 128
#define KG 26            // k-groups of 8 tf32 slots (208 slots, 201 real)
#define NTH 256

// SMEM layout (bytes)
#define ABYTES (KG*8*128*4)           // 106496
#define BBYTES (KG*4*128*4)           // 53248
#define B0_OFF ABYTES
#define SQ_OFF (B0_OFF + 2*BBYTES)    // 212992
#define SMEM_TOTAL (SQ_OFF + 2*BN*4)  // 213504

// Scratch: pre-split fragment images + |f2|^2
__device__ float g_sq2[B_ * N2_];
__device__ float g_Asplit[(size_t)B_ * MT * KG * 8 * 128];   // ~26 MB
__device__ float g_Bsplit[(size_t)B_ * NT * KG * 4 * 128];   // ~26 MB

// ---------------------------------------------------------------------------
__device__ __forceinline__ uint32_t f2tf(float x) {
    uint32_t r; asm("cvt.rna.tf32.f32 %0, %1;" : "=r"(r) : "f"(x)); return r;
}
struct Slot { int k; bool lo; bool valid; };
__device__ __forceinline__ Slot decodeB(int s) {
    Slot r; r.valid = s < 201; r.lo = (s >= 67 && s < 134);
    r.k = s < 67 ? s : (s < 134 ? s - 67 : s - 134); return r;
}
__device__ __forceinline__ Slot decodeA(int s) {
    Slot r; r.valid = s < 201; r.lo = (s >= 134 && s < 201);
    r.k = s < 67 ? s : (s < 134 ? s - 67 : s - 134); return r;
}
__device__ __forceinline__ const float* srcPtr(const float* P, const float* X,
                                               int k, int stride) {
    return k < D_ ? P + (size_t)k * stride : X + (size_t)(k - D_) * stride;
}
__device__ __forceinline__ uint32_t pick(float x, bool lo, bool valid) {
    if (!valid) return 0u;
    uint32_t hb = f2tf(x);
    if (!lo) return hb;
    float l = x - __uint_as_float(hb);
    return f2tf(l);
}

#define MMA8(C, A, b0v, b1v)                                              \
  asm volatile("mma.sync.aligned.m16n8k8.row.col.f32.tf32.tf32.f32 "      \
    "{%0,%1,%2,%3}, {%4,%5,%6,%7}, {%8,%9}, {%0,%1,%2,%3};"               \
    : "+f"((C)[0]), "+f"((C)[1]), "+f"((C)[2]), "+f"((C)[3])              \
    : "r"((A).x), "r"((A).y), "r"((A).z), "r"((A).w), "r"(b0v), "r"(b1v))

__device__ __forceinline__ uint32_t smem_u32(const void* p) {
    uint32_t a;
    asm("{ .reg .u64 t; cvta.to.shared.u64 t, %1; cvt.u32.u64 %0, t; }" : "=r"(a) : "l"(p));
    return a;
}
__device__ __forceinline__ void cpa16(uint32_t s, const void* g) {
    asm volatile("cp.async.cg.shared.global [%0], [%1], 16;" :: "r"(s), "l"(g) : "memory");
}
#define CP_COMMIT() asm volatile("cp.async.commit_group;" ::: "memory")
#define CP_WAIT0()  asm volatile("cp.async.wait_group 0;" ::: "memory")

// ---------------------------------------------------------------------------
__global__ void sq2_kernel(const float* __restrict__ xyz2,
                           const float* __restrict__ points2) {
    int idx = blockIdx.x * blockDim.x + threadIdx.x;
    if (idx >= B_ * N2_) return;
    int b = idx / N2_, j = idx % N2_;
    const float* p = points2 + (size_t)b * D_ * N2_ + j;
    float s = 0.f;
    #pragma unroll
    for (int d = 0; d < D_; d++) { float v = p[(size_t)d * N2_]; s += v * v; }
    const float* x = xyz2 + (size_t)b * 3 * N2_ + j;
    #pragma unroll
    for (int d = 0; d < 3; d++) { float v = x[(size_t)d * N2_]; s += v * v; }
    g_sq2[idx] = s;
}

// One warp per A block: write thread-major fragment image (layout == R3)
__global__ void prepA_kernel(const float* __restrict__ xyz1,
                             const float* __restrict__ points1) {
    int gw   = (blockIdx.x * blockDim.x + threadIdx.x) >> 5;
    int lane = threadIdx.x & 31;
    if (gw >= B_ * MT * KG * 8) return;
    int ab = gw % (KG * 8); int rem = gw / (KG * 8);
    int mt = rem % MT;      int b   = rem / MT;
    const float* P1 = points1 + (size_t)b * D_ * N1_;
    const float* X1 = xyz1    + (size_t)b * 3  * N1_;
    int g = ab >> 3, fA = ab & 7;
    int lr = lane >> 2, lc = lane & 3;
    int m1 = mt * BM + fA * 16 + lr;
    int s0 = g * 8 + lc, s1 = s0 + 4;
    Slot d0 = decodeA(s0), d1 = decodeA(s1);
    float xa = 0, xb = 0, xc = 0, xd = 0;
    if (d0.valid) { const float* p = srcPtr(P1, X1, d0.k, N1_); xa = p[m1]; xb = p[m1 + 8]; }
    if (d1.valid) { const float* p = srcPtr(P1, X1, d1.k, N1_); xc = p[m1]; xd = p[m1 + 8]; }
    uint4 v;
    v.x = pick(xa, d0.lo, d0.valid);
    v.y = pick(xb, d0.lo, d0.valid);
    v.z = pick(xc, d1.lo, d1.valid);
    v.w = pick(xd, d1.lo, d1.valid);
    ((uint4*)g_Asplit)[(size_t)gw * 32 + lane] = v;
}

// One warp per B superblock (layout == R3)
__global__ void prepB_kernel(const float* __restrict__ xyz2,
                             const float* __restrict__ points2) {
    int gw   = (blockIdx.x * blockDim.x + threadIdx.x) >> 5;
    int lane = threadIdx.x & 31;
    if (gw >= B_ * NT * KG * 4) return;
    int sb = gw % (KG * 4); int rem = gw / (KG * 4);
    int nt = rem % NT;      int b   = rem / NT;
    const float* P2 = points2 + (size_t)b * D_ * N2_;
    const float* X2 = xyz2    + (size_t)b * 3  * N2_;
    int kg = sb >> 2, q = sb & 3;
    int lr = lane >> 2, lc = lane & 3;
    int n1 = nt * BN + q * 16 + lr, n2 = n1 + 8;
    int s0 = kg * 8 + lc, s1 = s0 + 4;
    Slot d0 = decodeB(s0), d1 = decodeB(s1);
    float xa = 0, xb = 0, xc = 0, xd = 0;
    if (d0.valid) { const float* p = srcPtr(P2, X2, d0.k, N2_); xa = p[n1]; xc = p[n2]; }
    if (d1.valid) { const float* p = srcPtr(P2, X2, d1.k, N2_); xb = p[n1]; xd = p[n2]; }
    uint4 v;
    v.x = pick(xa, d0.lo, d0.valid);
    v.y = pick(xb, d1.lo, d1.valid);
    v.z = pick(xc, d0.lo, d0.valid);
    v.w = pick(xd, d1.lo, d1.valid);
    ((uint4*)g_Bsplit)[(size_t)gw * 32 + lane] = v;
}

// ---------------------------------------------------------------------------
// Main: lean MMA loop (LDS + MMA only), cp.async double-buffered B tiles.
// ---------------------------------------------------------------------------
__global__ void __launch_bounds__(NTH, 1)
nn_mma_kernel(const float* __restrict__ xyz1, const float* __restrict__ xyz2,
              float* __restrict__ out) {
    extern __shared__ char smem[];
    const uint32_t su = smem_u32(smem);
    const int tid  = threadIdx.x;
    const int w    = tid >> 5, lane = tid & 31;
    const int wr   = w >> 1, wc = w & 1;
    const int lr   = lane >> 2, lc = lane & 3;
    const int b    = blockIdx.y;
    const int mt   = blockIdx.x;
    const int m0   = mt * BM;

    const float* X1 = xyz1 + (size_t)b * 3 * N1_;
    const float* X2 = xyz2 + (size_t)b * 3 * N2_;
    float* shSq = (float*)(smem + SQ_OFF);

    // Prologue: A image (104KB) + B tile 0 (52KB) + sq tile 0
    const float* gA = g_Asplit + (size_t)(b * MT + mt) * (KG * 8 * 128);
    for (int i = tid; i < KG * 8 * 32; i += NTH) cpa16(su + i * 16, gA + i * 4);
    {
        const float* gB = g_Bsplit + (size_t)(b * NT + 0) * (KG * 4 * 128);
        for (int i = tid; i < KG * 4 * 32; i += NTH) cpa16(su + B0_OFF + i * 16, gB + i * 4);
        if (tid < BN / 4) cpa16(su + SQ_OFF + tid * 16, g_sq2 + b * N2_ + tid * 4);
    }
    CP_COMMIT();
    CP_WAIT0();
    __syncthreads();

    float bestV[4] = {FLT_MAX, FLT_MAX, FLT_MAX, FLT_MAX};
    int   bestI[4] = {0, 0, 0, 0};

    for (int t = 0; t < NT; t++) {
        const int cur = t & 1;
        char* bufC = smem + B0_OFF + cur * BBYTES;
        const uint32_t bufN = su + B0_OFF + (cur ^ 1) * BBYTES;

        // Prefetch next tile (overlaps with MMA below)
        if (t + 1 < NT) {
            const float* gB = g_Bsplit + (size_t)(b * NT + t + 1) * (KG * 4 * 128);
            for (int i = tid; i < KG * 4 * 32; i += NTH) cpa16(bufN + i * 16, gB + i * 4);
            if (tid < BN / 4)
                cpa16(su + SQ_OFF + (cur ^ 1) * BN * 4 + tid * 16,
                      g_sq2 + b * N2_ + (t + 1) * BN + tid * 4);
            CP_COMMIT();
        }

        float acc[2][4][4];
        #pragma unroll
        for (int f = 0; f < 2; f++)
            #pragma unroll
            for (int nf = 0; nf < 4; nf++)
                #pragma unroll
                for (int r = 0; r < 4; r++) acc[f][nf][r] = 0.f;

        #pragma unroll
        for (int g = 0; g < KG; g++) {
            uint4 ra0 = *(const uint4*)(smem + ((size_t)(g * 8 + wr * 2 + 0) * 128 + lane * 4) * 4);
            uint4 ra1 = *(const uint4*)(smem + ((size_t)(g * 8 + wr * 2 + 1) * 128 + lane * 4) * 4);
            uint4 rb0 = *(const uint4*)(bufC + ((size_t)(g * 4 + wc * 2 + 0) * 128 + lane * 4) * 4);
            uint4 rb1 = *(const uint4*)(bufC + ((size_t)(g * 4 + wc * 2 + 1) * 128 + lane * 4) * 4);
            MMA8(acc[0][0], ra0, rb0.x, rb0.y);
            MMA8(acc[0][1], ra0, rb0.z, rb0.w);
            MMA8(acc[0][2], ra0, rb1.x, rb1.y);
            MMA8(acc[0][3], ra0, rb1.z, rb1.w);
            MMA8(acc[1][0], ra1, rb0.x, rb0.y);
            MMA8(acc[1][1], ra1, rb0.z, rb0.w);
            MMA8(acc[1][2], ra1, rb1.x, rb1.y);
            MMA8(acc[1][3], ra1, rb1.z, rb1.w);
        }

        // Epilogue: score + running argmin (j ascending => first-min)
        #pragma unroll
        for (int f = 0; f < 2; f++)
            #pragma unroll
            for (int nf = 0; nf < 4; nf++) {
                int nb = wc * 32 + nf * 8 + 2 * lc;
                float s0 = shSq[cur * BN + nb];
                float s1 = shSq[cur * BN + nb + 1];
                int j0 = t * BN + nb;
                #pragma unroll
                for (int h = 0; h < 2; h++) {
                    int bi = f * 2 + h;
                    float sc0 = fmaf(-2.f, acc[f][nf][h * 2 + 0], s0);
                    float sc1 = fmaf(-2.f, acc[f][nf][h * 2 + 1], s1);
                    if (sc0 < bestV[bi]) { bestV[bi] = sc0; bestI[bi] = j0; }
                    if (sc1 < bestV[bi]) { bestV[bi] = sc1; bestI[bi] = j0 + 1; }
                }
            }

        CP_WAIT0();
        __syncthreads();
    }

    // Lane reduction across lc (4 candidates per row live in lanes sharing lr)
    #pragma unroll
    for (int off = 1; off <= 2; off <<= 1) {
        #pragma unroll
        for (int r = 0; r < 4; r++) {
            float ov = __shfl_xor_sync(0xffffffff, bestV[r], off);
            int   oi = __shfl_xor_sync(0xffffffff, bestI[r], off);
            if (ov < bestV[r] || (ov == bestV[r] && oi < bestI[r])) {
                bestV[r] = ov; bestI[r] = oi;
            }
        }
    }
    __syncthreads();
    float* sv = (float*)smem;
    int*   si = (int*)(smem + 128 * 2 * 4);
    if (lc == 0) {
        #pragma unroll
        for (int r = 0; r < 4; r++) {
            int row = wr * 32 + (r >> 1) * 16 + lr + (r & 1) * 8;
            sv[row * 2 + wc] = bestV[r];
            si[row * 2 + wc] = bestI[r];
        }
    }
    __syncthreads();

    if (tid < BM) {
        float v0 = sv[tid * 2], v1 = sv[tid * 2 + 1];
        int   i0 = si[tid * 2], i1 = si[tid * 2 + 1];
        int   bi = (v1 < v0 || (v1 == v0 && i1 < i0)) ? i1 : i0;
        int   gi = m0 + tid;
        out[b * N1_ + gi]        = (float)gi;
        out[(B_ + b) * N1_ + gi] = (float)bi;
        float* dir = out + 2 * B_ * N1_;
        #pragma unroll
        for (int d = 0; d < 3; d++)
            dir[((size_t)b * 3 + d) * N1_ + gi] =
                X2[(size_t)d * N2_ + bi] - X1[(size_t)d * N1_ + gi];
    }
}

// ---------------------------------------------------------------------------
extern "C" void kernel_launch(void* const* d_in, const int* in_sizes, int n_in,
                              void* d_out, int out_size) {
    const float* xyz1    = (const float*)d_in[0];
    const float* xyz2    = (const float*)d_in[1];
    const float* points1 = (const float*)d_in[2];
    const float* points2 = (const float*)d_in[3];
    float* out = (float*)d_out;

    sq2_kernel<<<(B_ * N2_ + 255) / 256, 256>>>(xyz2, points2);
    {
        int warpsA = B_ * MT * KG * 8;
        prepA_kernel<<<(warpsA * 32 + NTH - 1) / NTH, NTH>>>(xyz1, points1);
        int warpsB = B_ * NT * KG * 4;
        prepB_kernel<<<(warpsB * 32 + NTH - 1) / NTH, NTH>>>(xyz2, points2);
    }

    cudaFuncSetAttribute(nn_mma_kernel,
                         cudaFuncAttributeMaxDynamicSharedMemorySize,
                         SMEM_TOTAL);
    dim3 grid(MT, B_);
    nn_mma_kernel<<<grid, NTH, SMEM_TOTAL>>>(xyz1, xyz2, out);
}

// round 6
// speedup vs baseline: 5.7930x; 1.7827x over previous
#include <cuda_runtime.h>
#include <cuda_fp16.h>
#include <float.h>
#include <stdint.h>

// Problem constants
#define B_   2
#define D_   64
#define KDIM 67
#define N1_  16384
#define N2_  16384

#define BM 128
#define BN 64
#define NT (N2_/BN)      // 256
#define MT (N1_/BM)      // 128
#define KG 13            // k-groups of 16 fp16 slots (208 slots, 201 real)
#define NTH 256

// SMEM layout (bytes)
#define ABYTES (KG*8*512)             // 53248: 104 A-blocks of 512B
#define BBYTES (KG*4*512)             // 26624: 52 B-superblocks per buffer
#define B0_OFF ABYTES
#define SQ_OFF (B0_OFF + 2*BBYTES)    // 106496
#define SMEM_TOTAL (SQ_OFF + 2*BN*4)  // 107008 -> 2 CTAs/SM

// Scratch: pre-split fp16 fragment images + |f2|^2
__device__ float g_sq2[B_ * N2_];
__device__ float g_Asplit[(size_t)B_ * MT * KG * 8 * 128];   // 13.6 MB
__device__ float g_Bsplit[(size_t)B_ * NT * KG * 4 * 128];   // 13.6 MB

// ---------------------------------------------------------------------------
struct Slot { int k; bool lo; bool valid; };
__device__ __forceinline__ Slot decodeB(int s) {
    Slot r; r.valid = s < 201; r.lo = (s >= 67 && s < 134);
    r.k = s < 67 ? s : (s < 134 ? s - 67 : s - 134); return r;
}
__device__ __forceinline__ Slot decodeA(int s) {
    Slot r; r.valid = s < 201; r.lo = (s >= 134 && s < 201);
    r.k = s < 67 ? s : (s < 134 ? s - 67 : s - 134); return r;
}
__device__ __forceinline__ const float* srcPtr(const float* P, const float* X,
                                               int k, int stride) {
    return k < D_ ? P + (size_t)k * stride : X + (size_t)(k - D_) * stride;
}
// fp16 split: hi = rn(x); lo = rn(x - hi)
__device__ __forceinline__ uint16_t pickh(const float* P, const float* X,
                                          int stride, int idx, int s, bool isA) {
    Slot d = isA ? decodeA(s) : decodeB(s);
    if (!d.valid) return 0;
    float x = srcPtr(P, X, d.k, stride)[idx];
    __half h = __float2half_rn(x);
    if (!d.lo) return __half_as_ushort(h);
    float l = x - __half2float(h);
    return __half_as_ushort(__float2half_rn(l));
}
__device__ __forceinline__ uint32_t packh(uint16_t a, uint16_t b) {
    return (uint32_t)a | ((uint32_t)b << 16);
}

#define MMA16(C, A, b0v, b1v)                                             \
  asm volatile("mma.sync.aligned.m16n8k16.row.col.f32.f16.f16.f32 "       \
    "{%0,%1,%2,%3}, {%4,%5,%6,%7}, {%8,%9}, {%0,%1,%2,%3};"               \
    : "+f"((C)[0]), "+f"((C)[1]), "+f"((C)[2]), "+f"((C)[3])              \
    : "r"((A).x), "r"((A).y), "r"((A).z), "r"((A).w), "r"(b0v), "r"(b1v))

__device__ __forceinline__ uint32_t smem_u32(const void* p) {
    uint32_t a;
    asm("{ .reg .u64 t; cvta.to.shared.u64 t, %1; cvt.u32.u64 %0, t; }" : "=r"(a) : "l"(p));
    return a;
}
__device__ __forceinline__ void cpa16(uint32_t s, const void* g) {
    asm volatile("cp.async.cg.shared.global [%0], [%1], 16;" :: "r"(s), "l"(g) : "memory");
}
#define CP_COMMIT() asm volatile("cp.async.commit_group;" ::: "memory")
#define CP_WAIT0()  asm volatile("cp.async.wait_group 0;" ::: "memory")

// ---------------------------------------------------------------------------
__global__ void sq2_kernel(const float* __restrict__ xyz2,
                           const float* __restrict__ points2) {
    int idx = blockIdx.x * blockDim.x + threadIdx.x;
    if (idx >= B_ * N2_) return;
    int b = idx / N2_, j = idx % N2_;
    const float* p = points2 + (size_t)b * D_ * N2_ + j;
    float s = 0.f;
    #pragma unroll
    for (int d = 0; d < D_; d++) { float v = p[(size_t)d * N2_]; s += v * v; }
    const float* x = xyz2 + (size_t)b * 3 * N2_ + j;
    #pragma unroll
    for (int d = 0; d < 3; d++) { float v = x[(size_t)d * N2_]; s += v * v; }
    g_sq2[idx] = s;
}

// One warp per A block (16m x 16k'): m16n8k16 A-fragment image, thread-major
__global__ void prepA_kernel(const float* __restrict__ xyz1,
                             const float* __restrict__ points1) {
    int gw   = (blockIdx.x * blockDim.x + threadIdx.x) >> 5;
    int lane = threadIdx.x & 31;
    if (gw >= B_ * MT * KG * 8) return;
    int ab = gw % (KG * 8); int rem = gw / (KG * 8);
    int mt = rem % MT;      int b   = rem / MT;
    const float* P1 = points1 + (size_t)b * D_ * N1_;
    const float* X1 = xyz1    + (size_t)b * 3  * N1_;
    int g = ab >> 3, fA = ab & 7;
    int lr = lane >> 2, lc = lane & 3;
    int m1 = mt * BM + fA * 16 + lr, m2 = m1 + 8;
    int s0 = g * 16 + 2 * lc;
    uint4 v;
    v.x = packh(pickh(P1, X1, N1_, m1, s0,     true), pickh(P1, X1, N1_, m1, s0 + 1, true));
    v.y = packh(pickh(P1, X1, N1_, m2, s0,     true), pickh(P1, X1, N1_, m2, s0 + 1, true));
    v.z = packh(pickh(P1, X1, N1_, m1, s0 + 8, true), pickh(P1, X1, N1_, m1, s0 + 9, true));
    v.w = packh(pickh(P1, X1, N1_, m2, s0 + 8, true), pickh(P1, X1, N1_, m2, s0 + 9, true));
    ((uint4*)g_Asplit)[(size_t)gw * 32 + lane] = v;
}

// One warp per B superblock (16n x 16k'): two n8 B-fragments packed per lane
__global__ void prepB_kernel(const float* __restrict__ xyz2,
                             const float* __restrict__ points2) {
    int gw   = (blockIdx.x * blockDim.x + threadIdx.x) >> 5;
    int lane = threadIdx.x & 31;
    if (gw >= B_ * NT * KG * 4) return;
    int sb = gw % (KG * 4); int rem = gw / (KG * 4);
    int nt = rem % NT;      int b   = rem / NT;
    const float* P2 = points2 + (size_t)b * D_ * N2_;
    const float* X2 = xyz2    + (size_t)b * 3  * N2_;
    int g = sb >> 2, q = sb & 3;
    int lr = lane >> 2, lc = lane & 3;
    int n1 = nt * BN + q * 16 + lr, n2 = n1 + 8;
    int s0 = g * 16 + 2 * lc;
    uint4 v;
    v.x = packh(pickh(P2, X2, N2_, n1, s0,     false), pickh(P2, X2, N2_, n1, s0 + 1, false)); // b0 even
    v.y = packh(pickh(P2, X2, N2_, n1, s0 + 8, false), pickh(P2, X2, N2_, n1, s0 + 9, false)); // b1 even
    v.z = packh(pickh(P2, X2, N2_, n2, s0,     false), pickh(P2, X2, N2_, n2, s0 + 1, false)); // b0 odd
    v.w = packh(pickh(P2, X2, N2_, n2, s0 + 8, false), pickh(P2, X2, N2_, n2, s0 + 9, false)); // b1 odd
    ((uint4*)g_Bsplit)[(size_t)gw * 32 + lane] = v;
}

// ---------------------------------------------------------------------------
// Main: fp16 m16n8k16 MMA loop with register fragment prefetch.
// ---------------------------------------------------------------------------
__global__ void __launch_bounds__(NTH, 2)
nn_mma_kernel(const float* __restrict__ xyz1, const float* __restrict__ xyz2,
              float* __restrict__ out) {
    extern __shared__ char smem[];
    const uint32_t su = smem_u32(smem);
    const int tid  = threadIdx.x;
    const int w    = tid >> 5, lane = tid & 31;
    const int wr   = w >> 1, wc = w & 1;
    const int lr   = lane >> 2, lc = lane & 3;
    const int b    = blockIdx.y;
    const int mt   = blockIdx.x;
    const int m0   = mt * BM;

    const float* X1 = xyz1 + (size_t)b * 3 * N1_;
    const float* X2 = xyz2 + (size_t)b * 3 * N2_;
    float* shSq = (float*)(smem + SQ_OFF);

    // Prologue: A image (52KB) + B tile 0 (26KB) + sq tile 0
    const float* gA = g_Asplit + (size_t)(b * MT + mt) * (KG * 8 * 128);
    for (int i = tid; i < KG * 8 * 32; i += NTH) cpa16(su + i * 16, gA + i * 4);
    {
        const float* gB = g_Bsplit + (size_t)(b * NT + 0) * (KG * 4 * 128);
        for (int i = tid; i < KG * 4 * 32; i += NTH) cpa16(su + B0_OFF + i * 16, gB + i * 4);
        if (tid < BN / 4) cpa16(su + SQ_OFF + tid * 16, g_sq2 + b * N2_ + tid * 4);
    }
    CP_COMMIT();
    CP_WAIT0();
    __syncthreads();

    float bestV[4] = {FLT_MAX, FLT_MAX, FLT_MAX, FLT_MAX};
    int   bestI[4] = {0, 0, 0, 0};

    const char* aBase = smem + ((size_t)(wr * 2) * 512 + lane * 16);

    for (int t = 0; t < NT; t++) {
        const int cur = t & 1;
        const char* bBase = smem + B0_OFF + cur * BBYTES
                          + ((size_t)(wc * 2) * 512 + lane * 16);
        const uint32_t bufN = su + B0_OFF + (cur ^ 1) * BBYTES;

        if (t + 1 < NT) {
            const float* gB = g_Bsplit + (size_t)(b * NT + t + 1) * (KG * 4 * 128);
            for (int i = tid; i < KG * 4 * 32; i += NTH) cpa16(bufN + i * 16, gB + i * 4);
            if (tid < BN / 4)
                cpa16(su + SQ_OFF + (cur ^ 1) * BN * 4 + tid * 16,
                      g_sq2 + b * N2_ + (t + 1) * BN + tid * 4);
            CP_COMMIT();
        }

        float acc[2][4][4];
        #pragma unroll
        for (int f = 0; f < 2; f++)
            #pragma unroll
            for (int nf = 0; nf < 4; nf++)
                #pragma unroll
                for (int r = 0; r < 4; r++) acc[f][nf][r] = 0.f;

        // Register fragment prefetch pipeline
        uint4 ra0 = *(const uint4*)(aBase);
        uint4 ra1 = *(const uint4*)(aBase + 512);
        uint4 rb0 = *(const uint4*)(bBase);
        uint4 rb1 = *(const uint4*)(bBase + 512);

        #pragma unroll
        for (int g = 0; g < KG; g++) {
            uint4 na0 = ra0, na1 = ra1, nb0 = rb0, nb1 = rb1;
            if (g + 1 < KG) {
                na0 = *(const uint4*)(aBase + (size_t)(g + 1) * 8 * 512);
                na1 = *(const uint4*)(aBase + (size_t)(g + 1) * 8 * 512 + 512);
                nb0 = *(const uint4*)(bBase + (size_t)(g + 1) * 4 * 512);
                nb1 = *(const uint4*)(bBase + (size_t)(g + 1) * 4 * 512 + 512);
            }
            MMA16(acc[0][0], ra0, rb0.x, rb0.y);
            MMA16(acc[0][1], ra0, rb0.z, rb0.w);
            MMA16(acc[0][2], ra0, rb1.x, rb1.y);
            MMA16(acc[0][3], ra0, rb1.z, rb1.w);
            MMA16(acc[1][0], ra1, rb0.x, rb0.y);
            MMA16(acc[1][1], ra1, rb0.z, rb0.w);
            MMA16(acc[1][2], ra1, rb1.x, rb1.y);
            MMA16(acc[1][3], ra1, rb1.z, rb1.w);
            ra0 = na0; ra1 = na1; rb0 = nb0; rb1 = nb1;
        }

        // Epilogue: score = |f2|^2 - 2*dot, running argmin (j ascending)
        #pragma unroll
        for (int f = 0; f < 2; f++)
            #pragma unroll
            for (int nf = 0; nf < 4; nf++) {
                int nb = wc * 32 + nf * 8 + 2 * lc;
                float s0 = shSq[cur * BN + nb];
                float s1 = shSq[cur * BN + nb + 1];
                int j0 = t * BN + nb;
                #pragma unroll
                for (int h = 0; h < 2; h++) {
                    int bi = f * 2 + h;
                    float sc0 = fmaf(-2.f, acc[f][nf][h * 2 + 0], s0);
                    float sc1 = fmaf(-2.f, acc[f][nf][h * 2 + 1], s1);
                    if (sc0 < bestV[bi]) { bestV[bi] = sc0; bestI[bi] = j0; }
                    if (sc1 < bestV[bi]) { bestV[bi] = sc1; bestI[bi] = j0 + 1; }
                }
            }

        CP_WAIT0();
        __syncthreads();
    }

    // Lane reduction across lc (4 candidates per row in lanes sharing lr)
    #pragma unroll
    for (int off = 1; off <= 2; off <<= 1) {
        #pragma unroll
        for (int r = 0; r < 4; r++) {
            float ov = __shfl_xor_sync(0xffffffff, bestV[r], off);
            int   oi = __shfl_xor_sync(0xffffffff, bestI[r], off);
            if (ov < bestV[r] || (ov == bestV[r] && oi < bestI[r])) {
                bestV[r] = ov; bestI[r] = oi;
            }
        }
    }
    __syncthreads();
    float* sv = (float*)smem;
    int*   si = (int*)(smem + 128 * 2 * 4);
    if (lc == 0) {
        #pragma unroll
        for (int r = 0; r < 4; r++) {
            int row = wr * 32 + (r >> 1) * 16 + lr + (r & 1) * 8;
            sv[row * 2 + wc] = bestV[r];
            si[row * 2 + wc] = bestI[r];
        }
    }
    __syncthreads();

    if (tid < BM) {
        float v0 = sv[tid * 2], v1 = sv[tid * 2 + 1];
        int   i0 = si[tid * 2], i1 = si[tid * 2 + 1];
        int   bi = (v1 < v0 || (v1 == v0 && i1 < i0)) ? i1 : i0;
        int   gi = m0 + tid;
        out[b * N1_ + gi]        = (float)gi;
        out[(B_ + b) * N1_ + gi] = (float)bi;
        float* dir = out + 2 * B_ * N1_;
        #pragma unroll
        for (int d = 0; d < 3; d++)
            dir[((size_t)b * 3 + d) * N1_ + gi] =
                X2[(size_t)d * N2_ + bi] - X1[(size_t)d * N1_ + gi];
    }
}

// ---------------------------------------------------------------------------
extern "C" void kernel_launch(void* const* d_in, const int* in_sizes, int n_in,
                              void* d_out, int out_size) {
    const float* xyz1    = (const float*)d_in[0];
    const float* xyz2    = (const float*)d_in[1];
    const float* points1 = (const float*)d_in[2];
    const float* points2 = (const float*)d_in[3];
    float* out = (float*)d_out;

    sq2_kernel<<<(B_ * N2_ + 255) / 256, 256>>>(xyz2, points2);
    {
        int warpsA = B_ * MT * KG * 8;
        prepA_kernel<<<(warpsA * 32 + NTH - 1) / NTH, NTH>>>(xyz1, points1);
        int warpsB = B_ * NT * KG * 4;
        prepB_kernel<<<(warpsB * 32 + NTH - 1) / NTH, NTH>>>(xyz2, points2);
    }

    cudaFuncSetAttribute(nn_mma_kernel,
                         cudaFuncAttributeMaxDynamicSharedMemorySize,
                         SMEM_TOTAL);
    dim3 grid(MT, B_);
    nn_mma_kernel<<<grid, NTH, SMEM_TOTAL>>>(xyz1, xyz2, out);
}

// round 7
// speedup vs baseline: 6.1766x; 1.0662x over previous
#include <cuda_runtime.h>
#include <cuda_fp16.h>
#include <float.h>
#include <stdint.h>

// Problem constants
#define B_   2
#define D_   64
#define KDIM 67
#define N1_  16384
#define N2_  16384

#define BM 128
#define BN 64
#define NT (N2_/BN)      // 256
#define MT (N1_/BM)      // 128
#define KG 13            // k-groups of 16 fp16 slots (208 slots: 201 data + sq + pad)
#define NTH 256

// SMEM layout (bytes)
#define ABYTES (KG*8*512)             // 53248
#define BBYTES (KG*4*512)             // 26624
#define B0_OFF ABYTES
#define SMEM_TOTAL (ABYTES + 2*BBYTES)  // 106496 -> 2 CTAs/SM
#define NCH (KG*4*32)                 // 1664 16B-chunks per B tile

// Scratch
__device__ float g_sq2[B_ * N2_];
__device__ float g_Asplit[(size_t)B_ * MT * KG * 8 * 128];
__device__ float g_Bsplit[(size_t)B_ * NT * KG * 4 * 128];

// ---------------------------------------------------------------------------
struct Slot { int k; bool lo; bool valid; };
__device__ __forceinline__ Slot decodeB(int s) {
    Slot r; r.valid = s < 201; r.lo = (s >= 67 && s < 134);
    r.k = s < 67 ? s : (s < 134 ? s - 67 : s - 134); return r;
}
__device__ __forceinline__ Slot decodeA(int s) {
    Slot r; r.valid = s < 201; r.lo = (s >= 134 && s < 201);
    r.k = s < 67 ? s : (s < 134 ? s - 67 : s - 134); return r;
}
__device__ __forceinline__ const float* srcPtr(const float* P, const float* X,
                                               int k, int stride) {
    return k < D_ ? P + (size_t)k * stride : X + (size_t)(k - D_) * stride;
}
// A-side slot value: data hi/lo, or 1.0 in the two sq carrier slots
__device__ __forceinline__ uint16_t pickA(const float* P, const float* X,
                                          int idx, int s) {
    if (s == 201 || s == 202) return 0x3C00;   // 1.0h
    Slot d = decodeA(s);
    if (!d.valid) return 0;
    float x = srcPtr(P, X, d.k, N1_)[idx];
    __half h = __float2half_rn(x);
    if (!d.lo) return __half_as_ushort(h);
    return __half_as_ushort(__float2half_rn(x - __half2float(h)));
}
// B-side slot value: data hi/lo, or the two-part encoding of -sq_j/2
__device__ __forceinline__ uint16_t pickB(const float* P, const float* X,
                                          const float* SQ, int idx, int s) {
    if (s < 201) {
        Slot d = decodeB(s);
        float x = srcPtr(P, X, d.k, N2_)[idx];
        __half h = __float2half_rn(x);
        if (!d.lo) return __half_as_ushort(h);
        return __half_as_ushort(__float2half_rn(x - __half2float(h)));
    }
    if (s > 202) return 0;
    float v = -0.5f * SQ[idx];
    __half h = __float2half_rn(v);
    if (s == 201) return __half_as_ushort(h);
    return __half_as_ushort(__float2half_rn(v - __half2float(h)));
}
__device__ __forceinline__ uint32_t packh(uint16_t a, uint16_t b) {
    return (uint32_t)a | ((uint32_t)b << 16);
}

#define MMA16(C, A, b0v, b1v)                                             \
  asm volatile("mma.sync.aligned.m16n8k16.row.col.f32.f16.f16.f32 "       \
    "{%0,%1,%2,%3}, {%4,%5,%6,%7}, {%8,%9}, {%0,%1,%2,%3};"               \
    : "+f"((C)[0]), "+f"((C)[1]), "+f"((C)[2]), "+f"((C)[3])              \
    : "r"((A).x), "r"((A).y), "r"((A).z), "r"((A).w), "r"(b0v), "r"(b1v))

__device__ __forceinline__ uint32_t smem_u32(const void* p) {
    uint32_t a;
    asm("{ .reg .u64 t; cvta.to.shared.u64 t, %1; cvt.u32.u64 %0, t; }" : "=r"(a) : "l"(p));
    return a;
}
__device__ __forceinline__ void cpa16(uint32_t s, const void* g) {
    asm volatile("cp.async.cg.shared.global [%0], [%1], 16;" :: "r"(s), "l"(g) : "memory");
}
#define CP_COMMIT() asm volatile("cp.async.commit_group;" ::: "memory")
#define CP_WAIT0()  asm volatile("cp.async.wait_group 0;" ::: "memory")

// ---------------------------------------------------------------------------
__global__ void sq2_kernel(const float* __restrict__ xyz2,
                           const float* __restrict__ points2) {
    int idx = blockIdx.x * blockDim.x + threadIdx.x;
    if (idx >= B_ * N2_) return;
    int b = idx / N2_, j = idx % N2_;
    const float* p = points2 + (size_t)b * D_ * N2_ + j;
    float s = 0.f;
    #pragma unroll
    for (int d = 0; d < D_; d++) { float v = p[(size_t)d * N2_]; s += v * v; }
    const float* x = xyz2 + (size_t)b * 3 * N2_ + j;
    #pragma unroll
    for (int d = 0; d < 3; d++) { float v = x[(size_t)d * N2_]; s += v * v; }
    g_sq2[idx] = s;
}

// One warp per A block (16m x 16k'): m16n8k16 A-fragment image
__global__ void prepA_kernel(const float* __restrict__ xyz1,
                             const float* __restrict__ points1) {
    int gw   = (blockIdx.x * blockDim.x + threadIdx.x) >> 5;
    int lane = threadIdx.x & 31;
    if (gw >= B_ * MT * KG * 8) return;
    int ab = gw % (KG * 8); int rem = gw / (KG * 8);
    int mt = rem % MT;      int b   = rem / MT;
    const float* P1 = points1 + (size_t)b * D_ * N1_;
    const float* X1 = xyz1    + (size_t)b * 3  * N1_;
    int g = ab >> 3, fA = ab & 7;
    int lr = lane >> 2, lc = lane & 3;
    int m1 = mt * BM + fA * 16 + lr, m2 = m1 + 8;
    int s0 = g * 16 + 2 * lc;
    uint4 v;
    v.x = packh(pickA(P1, X1, m1, s0),     pickA(P1, X1, m1, s0 + 1));
    v.y = packh(pickA(P1, X1, m2, s0),     pickA(P1, X1, m2, s0 + 1));
    v.z = packh(pickA(P1, X1, m1, s0 + 8), pickA(P1, X1, m1, s0 + 9));
    v.w = packh(pickA(P1, X1, m2, s0 + 8), pickA(P1, X1, m2, s0 + 9));
    ((uint4*)g_Asplit)[(size_t)gw * 32 + lane] = v;
}

// One warp per B superblock (16n x 16k'); sq carried in slots 201/202
__global__ void prepB_kernel(const float* __restrict__ xyz2,
                             const float* __restrict__ points2) {
    int gw   = (blockIdx.x * blockDim.x + threadIdx.x) >> 5;
    int lane = threadIdx.x & 31;
    if (gw >= B_ * NT * KG * 4) return;
    int sb = gw % (KG * 4); int rem = gw / (KG * 4);
    int nt = rem % NT;      int b   = rem / NT;
    const float* P2 = points2 + (size_t)b * D_ * N2_;
    const float* X2 = xyz2    + (size_t)b * 3  * N2_;
    const float* SQ = g_sq2   + (size_t)b * N2_;
    int g = sb >> 2, q = sb & 3;
    int lr = lane >> 2, lc = lane & 3;
    int n1 = nt * BN + q * 16 + lr, n2 = n1 + 8;
    int s0 = g * 16 + 2 * lc;
    uint4 v;
    v.x = packh(pickB(P2, X2, SQ, n1, s0),     pickB(P2, X2, SQ, n1, s0 + 1));
    v.y = packh(pickB(P2, X2, SQ, n1, s0 + 8), pickB(P2, X2, SQ, n1, s0 + 9));
    v.z = packh(pickB(P2, X2, SQ, n2, s0),     pickB(P2, X2, SQ, n2, s0 + 1));
    v.w = packh(pickB(P2, X2, SQ, n2, s0 + 8), pickB(P2, X2, SQ, n2, s0 + 9));
    ((uint4*)g_Bsplit)[(size_t)gw * 32 + lane] = v;
}

// ---------------------------------------------------------------------------
// Main: fp16 MMA loop; acc = dot - sq/2 -> epilogue is pure argmax compare.
// B-tile cp.async spread across the k-loop (1 chunk-set per group).
// ---------------------------------------------------------------------------
__global__ void __launch_bounds__(NTH, 2)
nn_mma_kernel(const float* __restrict__ xyz1, const float* __restrict__ xyz2,
              float* __restrict__ out) {
    extern __shared__ char smem[];
    const uint32_t su = smem_u32(smem);
    const int tid  = threadIdx.x;
    const int w    = tid >> 5, lane = tid & 31;
    const int wr   = w >> 1, wc = w & 1;
    const int lr   = lane >> 2, lc = lane & 3;
    const int b    = blockIdx.y;
    const int mt   = blockIdx.x;
    const int m0   = mt * BM;

    const float* X1 = xyz1 + (size_t)b * 3 * N1_;
    const float* X2 = xyz2 + (size_t)b * 3 * N2_;

    // Prologue: A image + B tile 0
    const float* gA = g_Asplit + (size_t)(b * MT + mt) * (KG * 8 * 128);
    for (int i = tid; i < KG * 8 * 32; i += NTH) cpa16(su + i * 16, gA + i * 4);
    {
        const float* gB = g_Bsplit + (size_t)(b * NT) * (KG * 4 * 128);
        for (int i = tid; i < NCH; i += NTH) cpa16(su + B0_OFF + i * 16, gB + i * 4);
    }
    CP_COMMIT();
    CP_WAIT0();
    __syncthreads();

    float bestV[4] = {-FLT_MAX, -FLT_MAX, -FLT_MAX, -FLT_MAX};
    int   bestI[4] = {0, 0, 0, 0};

    const char* aBase = smem + ((size_t)(wr * 2) * 512 + lane * 16);

    for (int t = 0; t < NT; t++) {
        const int cur = t & 1;
        const char* bBase = smem + B0_OFF + cur * BBYTES
                          + ((size_t)(wc * 2) * 512 + lane * 16);
        const uint32_t bufN = su + B0_OFF + (cur ^ 1) * BBYTES;
        const float* gB = g_Bsplit + (size_t)(b * NT + t + 1) * (KG * 4 * 128);
        const bool pf = (t + 1 < NT);

        float acc[2][4][4];
        #pragma unroll
        for (int f = 0; f < 2; f++)
            #pragma unroll
            for (int nf = 0; nf < 4; nf++)
                #pragma unroll
                for (int r = 0; r < 4; r++) acc[f][nf][r] = 0.f;

        uint4 ra0 = *(const uint4*)(aBase);
        uint4 ra1 = *(const uint4*)(aBase + 512);
        uint4 rb0 = *(const uint4*)(bBase);
        uint4 rb1 = *(const uint4*)(bBase + 512);

        #pragma unroll
        for (int g = 0; g < KG; g++) {
            // Spread next-tile prefetch: one chunk-set per k-group
            if (pf && g < 7) {
                int i = g * NTH + tid;
                if (i < NCH) cpa16(bufN + i * 16, gB + i * 4);
            }
            uint4 na0 = ra0, na1 = ra1, nb0 = rb0, nb1 = rb1;
            if (g + 1 < KG) {
                na0 = *(const uint4*)(aBase + (size_t)(g + 1) * 8 * 512);
                na1 = *(const uint4*)(aBase + (size_t)(g + 1) * 8 * 512 + 512);
                nb0 = *(const uint4*)(bBase + (size_t)(g + 1) * 4 * 512);
                nb1 = *(const uint4*)(bBase + (size_t)(g + 1) * 4 * 512 + 512);
            }
            MMA16(acc[0][0], ra0, rb0.x, rb0.y);
            MMA16(acc[0][1], ra0, rb0.z, rb0.w);
            MMA16(acc[0][2], ra0, rb1.x, rb1.y);
            MMA16(acc[0][3], ra0, rb1.z, rb1.w);
            MMA16(acc[1][0], ra1, rb0.x, rb0.y);
            MMA16(acc[1][1], ra1, rb0.z, rb0.w);
            MMA16(acc[1][2], ra1, rb1.x, rb1.y);
            MMA16(acc[1][3], ra1, rb1.z, rb1.w);
            ra0 = na0; ra1 = na1; rb0 = nb0; rb1 = nb1;
        }
        if (pf) CP_COMMIT();

        // Epilogue: acc = dot - sq/2 ; argmax acc == argmin distance.
        // j ascending within a thread => strict '>' keeps first max.
        #pragma unroll
        for (int f = 0; f < 2; f++)
            #pragma unroll
            for (int nf = 0; nf < 4; nf++) {
                int j0 = t * BN + wc * 32 + nf * 8 + 2 * lc;
                #pragma unroll
                for (int h = 0; h < 2; h++) {
                    int bi = f * 2 + h;
                    float a0 = acc[f][nf][h * 2 + 0];
                    float a1 = acc[f][nf][h * 2 + 1];
                    if (a0 > bestV[bi]) { bestV[bi] = a0; bestI[bi] = j0; }
                    if (a1 > bestV[bi]) { bestV[bi] = a1; bestI[bi] = j0 + 1; }
                }
            }

        CP_WAIT0();
        __syncthreads();
    }

    // Lane reduction across lc (4 candidates per row in lanes sharing lr)
    #pragma unroll
    for (int off = 1; off <= 2; off <<= 1) {
        #pragma unroll
        for (int r = 0; r < 4; r++) {
            float ov = __shfl_xor_sync(0xffffffff, bestV[r], off);
            int   oi = __shfl_xor_sync(0xffffffff, bestI[r], off);
            if (ov > bestV[r] || (ov == bestV[r] && oi < bestI[r])) {
                bestV[r] = ov; bestI[r] = oi;
            }
        }
    }
    __syncthreads();
    float* sv = (float*)smem;
    int*   si = (int*)(smem + 128 * 2 * 4);
    if (lc == 0) {
        #pragma unroll
        for (int r = 0; r < 4; r++) {
            int row = wr * 32 + (r >> 1) * 16 + lr + (r & 1) * 8;
            sv[row * 2 + wc] = bestV[r];
            si[row * 2 + wc] = bestI[r];
        }
    }
    __syncthreads();

    if (tid < BM) {
        float v0 = sv[tid * 2], v1 = sv[tid * 2 + 1];
        int   i0 = si[tid * 2], i1 = si[tid * 2 + 1];
        int   bi = (v1 > v0 || (v1 == v0 && i1 < i0)) ? i1 : i0;
        int   gi = m0 + tid;
        out[b * N1_ + gi]        = (float)gi;
        out[(B_ + b) * N1_ + gi] = (float)bi;
        float* dir = out + 2 * B_ * N1_;
        #pragma unroll
        for (int d = 0; d < 3; d++)
            dir[((size_t)b * 3 + d) * N1_ + gi] =
                X2[(size_t)d * N2_ + bi] - X1[(size_t)d * N1_ + gi];
    }
}

// ---------------------------------------------------------------------------
extern "C" void kernel_launch(void* const* d_in, const int* in_sizes, int n_in,
                              void* d_out, int out_size) {
    const float* xyz1    = (const float*)d_in[0];
    const float* xyz2    = (const float*)d_in[1];
    const float* points1 = (const float*)d_in[2];
    const float* points2 = (const float*)d_in[3];
    float* out = (float*)d_out;

    sq2_kernel<<<(B_ * N2_ + 255) / 256, 256>>>(xyz2, points2);
    {
        int warpsA = B_ * MT * KG * 8;
        prepA_kernel<<<(warpsA * 32 + NTH - 1) / NTH, NTH>>>(xyz1, points1);
        int warpsB = B_ * NT * KG * 4;
        prepB_kernel<<<(warpsB * 32 + NTH - 1) / NTH, NTH>>>(xyz2, points2);
    }

    cudaFuncSetAttribute(nn_mma_kernel,
                         cudaFuncAttributeMaxDynamicSharedMemorySize,
                         SMEM_TOTAL);
    dim3 grid(MT, B_);
    nn_mma_kernel<<<grid, NTH, SMEM_TOTAL>>>(xyz1, xyz2, out);
}

// round 8
// speedup vs baseline: 6.9144x; 1.1194x over previous
#include <cuda_runtime.h>
#include <cuda_fp16.h>
#include <float.h>
#include <stdint.h>

// Problem constants
#define B_   2
#define D_   64
#define N1_  16384
#define N2_  16384

#define BM 128
#define BN 64
#define NT (N2_/BN)      // 256
#define MT (N1_/BM)      // 128
#define GA 9             // A k-groups stored: 4 H + 4 L + 1 xyz/sq
#define GB 9             // B k-groups stored: 4 H + 4 L + 1 xyz/sq
#define NTH 256

// SMEM layout (bytes)
#define ABYTES (GA*8*512)             // 36864
#define BBYTES (GB*4*512)             // 18432
#define B0_OFF ABYTES
#define SMEM_TOTAL (ABYTES + 2*BBYTES)  // 73728 -> 2 CTAs/SM easily
#define NCHB (BBYTES/16)              // 1152 chunks per B tile

// Scratch
__device__ float g_sq2[B_ * N2_];
__device__ float g_Asplit[(size_t)B_ * MT * GA * 8 * 128];   // 9.4 MB
__device__ float g_Bsplit[(size_t)B_ * NT * GB * 4 * 128];   // 9.4 MB

// ---------------------------------------------------------------------------
__device__ __forceinline__ uint16_t hi_h(float x) {
    return __half_as_ushort(__float2half_rn(x));
}
__device__ __forceinline__ uint16_t lo_h(float x) {
    __half h = __float2half_rn(x);
    return __half_as_ushort(__float2half_rn(x - __half2float(h)));
}
// A slot value: group ga, local slot sl, point-row m
__device__ __forceinline__ uint16_t slotA(const float* P1, const float* X1,
                                          int ga, int sl, int m) {
    if (ga < 4)  return hi_h(P1[(size_t)(ga * 16 + sl) * N1_ + m]);
    if (ga < 8)  return lo_h(P1[(size_t)((ga - 4) * 16 + sl) * N1_ + m]);
    // group 8: [xh yh zh | xl yl zl | xh yh zh | 1 1 | 0...]
    if (sl < 3)  return hi_h(X1[(size_t)sl * N1_ + m]);
    if (sl < 6)  return lo_h(X1[(size_t)(sl - 3) * N1_ + m]);
    if (sl < 9)  return hi_h(X1[(size_t)(sl - 6) * N1_ + m]);
    if (sl < 11) return 0x3C00;  // 1.0h (sq carriers)
    return 0;
}
// B slot value: group gb, local slot sl, point-col n
__device__ __forceinline__ uint16_t slotB(const float* P2, const float* X2,
                                          const float* SQ, int gb, int sl, int n) {
    if (gb < 4)  return hi_h(P2[(size_t)(gb * 16 + sl) * N2_ + n]);
    if (gb < 8)  return lo_h(P2[(size_t)((gb - 4) * 16 + sl) * N2_ + n]);
    // group 8: [xh yh zh | xh yh zh | xl yl zl | sqh sql | 0...]
    if (sl < 3)  return hi_h(X2[(size_t)sl * N2_ + n]);
    if (sl < 6)  return hi_h(X2[(size_t)(sl - 3) * N2_ + n]);
    if (sl < 9)  return lo_h(X2[(size_t)(sl - 6) * N2_ + n]);
    float v = -0.5f * SQ[n];
    if (sl == 9)  return hi_h(v);
    if (sl == 10) return lo_h(v);
    return 0;
}
__device__ __forceinline__ uint32_t packh(uint16_t a, uint16_t b) {
    return (uint32_t)a | ((uint32_t)b << 16);
}

#define MMA16(C, A, b0v, b1v)                                             \
  asm volatile("mma.sync.aligned.m16n8k16.row.col.f32.f16.f16.f32 "       \
    "{%0,%1,%2,%3}, {%4,%5,%6,%7}, {%8,%9}, {%0,%1,%2,%3};"               \
    : "+f"((C)[0]), "+f"((C)[1]), "+f"((C)[2]), "+f"((C)[3])              \
    : "r"((A).x), "r"((A).y), "r"((A).z), "r"((A).w), "r"(b0v), "r"(b1v))

__device__ __forceinline__ uint32_t smem_u32(const void* p) {
    uint32_t a;
    asm("{ .reg .u64 t; cvta.to.shared.u64 t, %1; cvt.u32.u64 %0, t; }" : "=r"(a) : "l"(p));
    return a;
}
__device__ __forceinline__ void cpa16(uint32_t s, const void* g) {
    asm volatile("cp.async.cg.shared.global [%0], [%1], 16;" :: "r"(s), "l"(g) : "memory");
}
#define CP_COMMIT() asm volatile("cp.async.commit_group;" ::: "memory")
#define CP_WAIT0()  asm volatile("cp.async.wait_group 0;" ::: "memory")

// ---------------------------------------------------------------------------
__global__ void sq2_kernel(const float* __restrict__ xyz2,
                           const float* __restrict__ points2) {
    int idx = blockIdx.x * blockDim.x + threadIdx.x;
    if (idx >= B_ * N2_) return;
    int b = idx / N2_, j = idx % N2_;
    const float* p = points2 + (size_t)b * D_ * N2_ + j;
    float s = 0.f;
    #pragma unroll
    for (int d = 0; d < D_; d++) { float v = p[(size_t)d * N2_]; s += v * v; }
    const float* x = xyz2 + (size_t)b * 3 * N2_ + j;
    #pragma unroll
    for (int d = 0; d < 3; d++) { float v = x[(size_t)d * N2_]; s += v * v; }
    g_sq2[idx] = s;
}

// One warp per A block (16m x 16k slots of group ga)
__global__ void prepA_kernel(const float* __restrict__ xyz1,
                             const float* __restrict__ points1) {
    int gw   = (blockIdx.x * blockDim.x + threadIdx.x) >> 5;
    int lane = threadIdx.x & 31;
    if (gw >= B_ * MT * GA * 8) return;
    int ab = gw % (GA * 8); int rem = gw / (GA * 8);
    int mt = rem % MT;      int b   = rem / MT;
    const float* P1 = points1 + (size_t)b * D_ * N1_;
    const float* X1 = xyz1    + (size_t)b * 3  * N1_;
    int ga = ab >> 3, fA = ab & 7;
    int lr = lane >> 2, lc = lane & 3;
    int m1 = mt * BM + fA * 16 + lr, m2 = m1 + 8;
    int s0 = 2 * lc;
    uint4 v;
    v.x = packh(slotA(P1, X1, ga, s0,     m1), slotA(P1, X1, ga, s0 + 1, m1));
    v.y = packh(slotA(P1, X1, ga, s0,     m2), slotA(P1, X1, ga, s0 + 1, m2));
    v.z = packh(slotA(P1, X1, ga, s0 + 8, m1), slotA(P1, X1, ga, s0 + 9, m1));
    v.w = packh(slotA(P1, X1, ga, s0 + 8, m2), slotA(P1, X1, ga, s0 + 9, m2));
    ((uint4*)g_Asplit)[(size_t)gw * 32 + lane] = v;
}

// One warp per B superblock (16n x 16k slots of group gb)
__global__ void prepB_kernel(const float* __restrict__ xyz2,
                             const float* __restrict__ points2) {
    int gw   = (blockIdx.x * blockDim.x + threadIdx.x) >> 5;
    int lane = threadIdx.x & 31;
    if (gw >= B_ * NT * GB * 4) return;
    int sb = gw % (GB * 4); int rem = gw / (GB * 4);
    int nt = rem % NT;      int b   = rem / NT;
    const float* P2 = points2 + (size_t)b * D_ * N2_;
    const float* X2 = xyz2    + (size_t)b * 3  * N2_;
    const float* SQ = g_sq2   + (size_t)b * N2_;
    int gb = sb >> 2, q = sb & 3;
    int lr = lane >> 2, lc = lane & 3;
    int n1 = nt * BN + q * 16 + lr, n2 = n1 + 8;
    int s0 = 2 * lc;
    uint4 v;
    v.x = packh(slotB(P2, X2, SQ, gb, s0,     n1), slotB(P2, X2, SQ, gb, s0 + 1, n1));
    v.y = packh(slotB(P2, X2, SQ, gb, s0 + 8, n1), slotB(P2, X2, SQ, gb, s0 + 9, n1));
    v.z = packh(slotB(P2, X2, SQ, gb, s0,     n2), slotB(P2, X2, SQ, gb, s0 + 1, n2));
    v.w = packh(slotB(P2, X2, SQ, gb, s0 + 8, n2), slotB(P2, X2, SQ, gb, s0 + 9, n2));
    ((uint4*)g_Bsplit)[(size_t)gw * 32 + lane] = v;
}

// ---------------------------------------------------------------------------
// Main: fp16 MMA loop with register-level 3-term reuse.
// Per 16-dim group: 8 LDS.128 feed 24 MMAs (H.H, L.H, H.L). xyz group: 4 LDS, 8 MMAs.
// ---------------------------------------------------------------------------
__global__ void __launch_bounds__(NTH, 2)
nn_mma_kernel(const float* __restrict__ xyz1, const float* __restrict__ xyz2,
              float* __restrict__ out) {
    extern __shared__ char smem[];
    const uint32_t su = smem_u32(smem);
    const int tid  = threadIdx.x;
    const int w    = tid >> 5, lane = tid & 31;
    const int wr   = w >> 1, wc = w & 1;
    const int lr   = lane >> 2, lc = lane & 3;
    const int b    = blockIdx.y;
    const int mt   = blockIdx.x;
    const int m0   = mt * BM;

    const float* X1 = xyz1 + (size_t)b * 3 * N1_;
    const float* X2 = xyz2 + (size_t)b * 3 * N2_;

    // Prologue: A image + B tile 0
    const float* gA = g_Asplit + (size_t)(b * MT + mt) * (GA * 8 * 128);
    for (int i = tid; i < ABYTES / 16; i += NTH) cpa16(su + i * 16, gA + i * 4);
    {
        const float* gB = g_Bsplit + (size_t)(b * NT) * (GB * 4 * 128);
        for (int i = tid; i < NCHB; i += NTH) cpa16(su + B0_OFF + i * 16, gB + i * 4);
    }
    CP_COMMIT();
    CP_WAIT0();
    __syncthreads();

    float bestV[4] = {-FLT_MAX, -FLT_MAX, -FLT_MAX, -FLT_MAX};
    int   bestI[4] = {0, 0, 0, 0};

    const char* aB = smem + (size_t)lane * 16;

    for (int t = 0; t < NT; t++) {
        const int cur = t & 1;
        const char* bB = smem + B0_OFF + cur * BBYTES + (size_t)lane * 16;
        const uint32_t bufN = su + B0_OFF + (cur ^ 1) * BBYTES;
        const float* gB = g_Bsplit + (size_t)(b * NT + t + 1) * (GB * 4 * 128);
        const bool pf = (t + 1 < NT);

        float acc[2][4][4];
        #pragma unroll
        for (int f = 0; f < 2; f++)
            #pragma unroll
            for (int nf = 0; nf < 4; nf++)
                #pragma unroll
                for (int r = 0; r < 4; r++) acc[f][nf][r] = 0.f;

        // 4 point-dim groups: 3-term reuse
        #pragma unroll
        for (int g = 0; g < 4; g++) {
            if (pf) {   // spread next-tile prefetch: one chunk-set per group
                int i = g * NTH + tid;
                if (i < NCHB) cpa16(bufN + i * 16, gB + i * 4);
            }
            uint4 aH0 = *(const uint4*)(aB + ((size_t)(g * 8       + wr * 2 + 0)) * 512);
            uint4 aH1 = *(const uint4*)(aB + ((size_t)(g * 8       + wr * 2 + 1)) * 512);
            uint4 aL0 = *(const uint4*)(aB + ((size_t)((4 + g) * 8 + wr * 2 + 0)) * 512);
            uint4 aL1 = *(const uint4*)(aB + ((size_t)((4 + g) * 8 + wr * 2 + 1)) * 512);
            uint4 bH0 = *(const uint4*)(bB + ((size_t)(g * 4       + wc * 2 + 0)) * 512);
            uint4 bH1 = *(const uint4*)(bB + ((size_t)(g * 4       + wc * 2 + 1)) * 512);
            uint4 bL0 = *(const uint4*)(bB + ((size_t)((4 + g) * 4 + wc * 2 + 0)) * 512);
            uint4 bL1 = *(const uint4*)(bB + ((size_t)((4 + g) * 4 + wc * 2 + 1)) * 512);
            // H.H
            MMA16(acc[0][0], aH0, bH0.x, bH0.y);
            MMA16(acc[0][1], aH0, bH0.z, bH0.w);
            MMA16(acc[0][2], aH0, bH1.x, bH1.y);
            MMA16(acc[0][3], aH0, bH1.z, bH1.w);
            MMA16(acc[1][0], aH1, bH0.x, bH0.y);
            MMA16(acc[1][1], aH1, bH0.z, bH0.w);
            MMA16(acc[1][2], aH1, bH1.x, bH1.y);
            MMA16(acc[1][3], aH1, bH1.z, bH1.w);
            // L.H
            MMA16(acc[0][0], aL0, bH0.x, bH0.y);
            MMA16(acc[0][1], aL0, bH0.z, bH0.w);
            MMA16(acc[0][2], aL0, bH1.x, bH1.y);
            MMA16(acc[0][3], aL0, bH1.z, bH1.w);
            MMA16(acc[1][0], aL1, bH0.x, bH0.y);
            MMA16(acc[1][1], aL1, bH0.z, bH0.w);
            MMA16(acc[1][2], aL1, bH1.x, bH1.y);
            MMA16(acc[1][3], aL1, bH1.z, bH1.w);
            // H.L
            MMA16(acc[0][0], aH0, bL0.x, bL0.y);
            MMA16(acc[0][1], aH0, bL0.z, bL0.w);
            MMA16(acc[0][2], aH0, bL1.x, bL1.y);
            MMA16(acc[0][3], aH0, bL1.z, bL1.w);
            MMA16(acc[1][0], aH1, bL0.x, bL0.y);
            MMA16(acc[1][1], aH1, bL0.z, bL0.w);
            MMA16(acc[1][2], aH1, bL1.x, bL1.y);
            MMA16(acc[1][3], aH1, bL1.z, bL1.w);
        }
        // xyz + sq group (ga=8, gb=8)
        {
            if (pf) {
                int i = 4 * NTH + tid;
                if (i < NCHB) cpa16(bufN + i * 16, gB + i * 4);
            }
            uint4 a0 = *(const uint4*)(aB + ((size_t)(64 + wr * 2 + 0)) * 512);
            uint4 a1 = *(const uint4*)(aB + ((size_t)(64 + wr * 2 + 1)) * 512);
            uint4 b0 = *(const uint4*)(bB + ((size_t)(32 + wc * 2 + 0)) * 512);
            uint4 b1 = *(const uint4*)(bB + ((size_t)(32 + wc * 2 + 1)) * 512);
            MMA16(acc[0][0], a0, b0.x, b0.y);
            MMA16(acc[0][1], a0, b0.z, b0.w);
            MMA16(acc[0][2], a0, b1.x, b1.y);
            MMA16(acc[0][3], a0, b1.z, b1.w);
            MMA16(acc[1][0], a1, b0.x, b0.y);
            MMA16(acc[1][1], a1, b0.z, b0.w);
            MMA16(acc[1][2], a1, b1.x, b1.y);
            MMA16(acc[1][3], a1, b1.z, b1.w);
        }
        if (pf) CP_COMMIT();

        // Epilogue: acc = dot - sq/2. Per-row max tree + rare index recovery.
        #pragma unroll
        for (int f = 0; f < 2; f++)
            #pragma unroll
            for (int h = 0; h < 2; h++) {
                const int bi = f * 2 + h;
                float m01 = fmaxf(acc[f][0][h * 2], acc[f][0][h * 2 + 1]);
                float m23 = fmaxf(acc[f][1][h * 2], acc[f][1][h * 2 + 1]);
                float m45 = fmaxf(acc[f][2][h * 2], acc[f][2][h * 2 + 1]);
                float m67 = fmaxf(acc[f][3][h * 2], acc[f][3][h * 2 + 1]);
                float m = fmaxf(fmaxf(m01, m23), fmaxf(m45, m67));
                if (m > bestV[bi]) {       // rare after early tiles
                    bestV[bi] = m;
                    int jj = 0;
                    #pragma unroll
                    for (int nf = 3; nf >= 0; nf--)
                        #pragma unroll
                        for (int c = 1; c >= 0; c--)
                            if (acc[f][nf][h * 2 + c] == m)
                                jj = t * BN + wc * 32 + nf * 8 + 2 * lc + c;
                    bestI[bi] = jj;        // descending scan => first (smallest) j
                }
            }

        CP_WAIT0();
        __syncthreads();
    }

    // Lane reduction across lc (4 candidates per row in lanes sharing lr)
    #pragma unroll
    for (int off = 1; off <= 2; off <<= 1) {
        #pragma unroll
        for (int r = 0; r < 4; r++) {
            float ov = __shfl_xor_sync(0xffffffff, bestV[r], off);
            int   oi = __shfl_xor_sync(0xffffffff, bestI[r], off);
            if (ov > bestV[r] || (ov == bestV[r] && oi < bestI[r])) {
                bestV[r] = ov; bestI[r] = oi;
            }
        }
    }
    __syncthreads();
    float* sv = (float*)smem;
    int*   si = (int*)(smem + 128 * 2 * 4);
    if (lc == 0) {
        #pragma unroll
        for (int r = 0; r < 4; r++) {
            int row = wr * 32 + (r >> 1) * 16 + lr + (r & 1) * 8;
            sv[row * 2 + wc] = bestV[r];
            si[row * 2 + wc] = bestI[r];
        }
    }
    __syncthreads();

    if (tid < BM) {
        float v0 = sv[tid * 2], v1 = sv[tid * 2 + 1];
        int   i0 = si[tid * 2], i1 = si[tid * 2 + 1];
        int   bi = (v1 > v0 || (v1 == v0 && i1 < i0)) ? i1 : i0;
        int   gi = m0 + tid;
        out[b * N1_ + gi]        = (float)gi;
        out[(B_ + b) * N1_ + gi] = (float)bi;
        float* dir = out + 2 * B_ * N1_;
        #pragma unroll
        for (int d = 0; d < 3; d++)
            dir[((size_t)b * 3 + d) * N1_ + gi] =
                X2[(size_t)d * N2_ + bi] - X1[(size_t)d * N1_ + gi];
    }
}

// ---------------------------------------------------------------------------
extern "C" void kernel_launch(void* const* d_in, const int* in_sizes, int n_in,
                              void* d_out, int out_size) {
    const float* xyz1    = (const float*)d_in[0];
    const float* xyz2    = (const float*)d_in[1];
    const float* points1 = (const float*)d_in[2];
    const float* points2 = (const float*)d_in[3];
    float* out = (float*)d_out;

    sq2_kernel<<<(B_ * N2_ + 255) / 256, 256>>>(xyz2, points2);
    {
        int warpsA = B_ * MT * GA * 8;
        prepA_kernel<<<(warpsA * 32 + NTH - 1) / NTH, NTH>>>(xyz1, points1);
        int warpsB = B_ * NT * GB * 4;
        prepB_kernel<<<(warpsB * 32 + NTH - 1) / NTH, NTH>>>(xyz2, points2);
    }

    cudaFuncSetAttribute(nn_mma_kernel,
                         cudaFuncAttributeMaxDynamicSharedMemorySize,
                         SMEM_TOTAL);
    dim3 grid(MT, B_);
    nn_mma_kernel<<<grid, NTH, SMEM_TOTAL>>>(xyz1, xyz2, out);
}

// round 9
// speedup vs baseline: 7.1510x; 1.0342x over previous
#include <cuda_runtime.h>
#include <cuda_fp16.h>
#include <float.h>
#include <stdint.h>

// Problem constants
#define B_   2
#define D_   64
#define N1_  16384
#define N2_  16384

#define BM 128
#define BN 64
#define NT (N2_/BN)      // 256
#define MT (N1_/BM)      // 128
#define GA 9             // A k-groups stored: 4 H + 4 L + 1 xyz/sq
#define GB 9             // B k-groups stored: 4 H + 4 L + 1 xyz/sq
#define NTH 256

// SMEM layout (bytes): A image + 4-deep B ring
#define ABYTES (GA*8*512)             // 36864
#define BBYTES (GB*4*512)             // 18432
#define B0_OFF ABYTES
#define SMEM_TOTAL (ABYTES + 4*BBYTES)  // 110592 -> 2 CTAs/SM
#define NCHB (BBYTES/16)              // 1152 chunks per B tile

// Scratch
__device__ float g_sq2[B_ * N2_];
__device__ float g_Asplit[(size_t)B_ * MT * GA * 8 * 128];
__device__ float g_Bsplit[(size_t)B_ * NT * GB * 4 * 128];

// ---------------------------------------------------------------------------
__device__ __forceinline__ uint16_t hi_h(float x) {
    return __half_as_ushort(__float2half_rn(x));
}
__device__ __forceinline__ uint16_t lo_h(float x) {
    __half h = __float2half_rn(x);
    return __half_as_ushort(__float2half_rn(x - __half2float(h)));
}
__device__ __forceinline__ uint16_t slotA(const float* P1, const float* X1,
                                          int ga, int sl, int m) {
    if (ga < 4)  return hi_h(P1[(size_t)(ga * 16 + sl) * N1_ + m]);
    if (ga < 8)  return lo_h(P1[(size_t)((ga - 4) * 16 + sl) * N1_ + m]);
    if (sl < 3)  return hi_h(X1[(size_t)sl * N1_ + m]);
    if (sl < 6)  return lo_h(X1[(size_t)(sl - 3) * N1_ + m]);
    if (sl < 9)  return hi_h(X1[(size_t)(sl - 6) * N1_ + m]);
    if (sl < 11) return 0x3C00;  // 1.0h (sq carriers)
    return 0;
}
__device__ __forceinline__ uint16_t slotB(const float* P2, const float* X2,
                                          const float* SQ, int gb, int sl, int n) {
    if (gb < 4)  return hi_h(P2[(size_t)(gb * 16 + sl) * N2_ + n]);
    if (gb < 8)  return lo_h(P2[(size_t)((gb - 4) * 16 + sl) * N2_ + n]);
    if (sl < 3)  return hi_h(X2[(size_t)sl * N2_ + n]);
    if (sl < 6)  return hi_h(X2[(size_t)(sl - 3) * N2_ + n]);
    if (sl < 9)  return lo_h(X2[(size_t)(sl - 6) * N2_ + n]);
    float v = -0.5f * SQ[n];
    if (sl == 9)  return hi_h(v);
    if (sl == 10) return lo_h(v);
    return 0;
}
__device__ __forceinline__ uint32_t packh(uint16_t a, uint16_t b) {
    return (uint32_t)a | ((uint32_t)b << 16);
}

#define MMA16(C, A, b0v, b1v)                                             \
  asm volatile("mma.sync.aligned.m16n8k16.row.col.f32.f16.f16.f32 "       \
    "{%0,%1,%2,%3}, {%4,%5,%6,%7}, {%8,%9}, {%0,%1,%2,%3};"               \
    : "+f"((C)[0]), "+f"((C)[1]), "+f"((C)[2]), "+f"((C)[3])              \
    : "r"((A).x), "r"((A).y), "r"((A).z), "r"((A).w), "r"(b0v), "r"(b1v))

__device__ __forceinline__ uint32_t smem_u32(const void* p) {
    uint32_t a;
    asm("{ .reg .u64 t; cvta.to.shared.u64 t, %1; cvt.u32.u64 %0, t; }" : "=r"(a) : "l"(p));
    return a;
}
__device__ __forceinline__ void cpa16(uint32_t s, const void* g) {
    asm volatile("cp.async.cg.shared.global [%0], [%1], 16;" :: "r"(s), "l"(g) : "memory");
}
#define CP_COMMIT() asm volatile("cp.async.commit_group;" ::: "memory")
#define CP_WAIT0()  asm volatile("cp.async.wait_group 0;" ::: "memory")

// ---------------------------------------------------------------------------
__global__ void sq2_kernel(const float* __restrict__ xyz2,
                           const float* __restrict__ points2) {
    int idx = blockIdx.x * blockDim.x + threadIdx.x;
    if (idx >= B_ * N2_) return;
    int b = idx / N2_, j = idx % N2_;
    const float* p = points2 + (size_t)b * D_ * N2_ + j;
    float s = 0.f;
    #pragma unroll
    for (int d = 0; d < D_; d++) { float v = p[(size_t)d * N2_]; s += v * v; }
    const float* x = xyz2 + (size_t)b * 3 * N2_ + j;
    #pragma unroll
    for (int d = 0; d < 3; d++) { float v = x[(size_t)d * N2_]; s += v * v; }
    g_sq2[idx] = s;
}

__global__ void prepA_kernel(const float* __restrict__ xyz1,
                             const float* __restrict__ points1) {
    int gw   = (blockIdx.x * blockDim.x + threadIdx.x) >> 5;
    int lane = threadIdx.x & 31;
    if (gw >= B_ * MT * GA * 8) return;
    int ab = gw % (GA * 8); int rem = gw / (GA * 8);
    int mt = rem % MT;      int b   = rem / MT;
    const float* P1 = points1 + (size_t)b * D_ * N1_;
    const float* X1 = xyz1    + (size_t)b * 3  * N1_;
    int ga = ab >> 3, fA = ab & 7;
    int lr = lane >> 2, lc = lane & 3;
    int m1 = mt * BM + fA * 16 + lr, m2 = m1 + 8;
    int s0 = 2 * lc;
    uint4 v;
    v.x = packh(slotA(P1, X1, ga, s0,     m1), slotA(P1, X1, ga, s0 + 1, m1));
    v.y = packh(slotA(P1, X1, ga, s0,     m2), slotA(P1, X1, ga, s0 + 1, m2));
    v.z = packh(slotA(P1, X1, ga, s0 + 8, m1), slotA(P1, X1, ga, s0 + 9, m1));
    v.w = packh(slotA(P1, X1, ga, s0 + 8, m2), slotA(P1, X1, ga, s0 + 9, m2));
    ((uint4*)g_Asplit)[(size_t)gw * 32 + lane] = v;
}

__global__ void prepB_kernel(const float* __restrict__ xyz2,
                             const float* __restrict__ points2) {
    int gw   = (blockIdx.x * blockDim.x + threadIdx.x) >> 5;
    int lane = threadIdx.x & 31;
    if (gw >= B_ * NT * GB * 4) return;
    int sb = gw % (GB * 4); int rem = gw / (GB * 4);
    int nt = rem % NT;      int b   = rem / NT;
    const float* P2 = points2 + (size_t)b * D_ * N2_;
    const float* X2 = xyz2    + (size_t)b * 3  * N2_;
    const float* SQ = g_sq2   + (size_t)b * N2_;
    int gb = sb >> 2, q = sb & 3;
    int lr = lane >> 2, lc = lane & 3;
    int n1 = nt * BN + q * 16 + lr, n2 = n1 + 8;
    int s0 = 2 * lc;
    uint4 v;
    v.x = packh(slotB(P2, X2, SQ, gb, s0,     n1), slotB(P2, X2, SQ, gb, s0 + 1, n1));
    v.y = packh(slotB(P2, X2, SQ, gb, s0 + 8, n1), slotB(P2, X2, SQ, gb, s0 + 9, n1));
    v.z = packh(slotB(P2, X2, SQ, gb, s0,     n2), slotB(P2, X2, SQ, gb, s0 + 1, n2));
    v.w = packh(slotB(P2, X2, SQ, gb, s0 + 8, n2), slotB(P2, X2, SQ, gb, s0 + 9, n2));
    ((uint4*)g_Bsplit)[(size_t)gw * 32 + lane] = v;
}

// ---------------------------------------------------------------------------
// Main: 2 tiles per iteration, single barrier per iteration, 4-buffer ring.
// ---------------------------------------------------------------------------
__global__ void __launch_bounds__(NTH, 2)
nn_mma_kernel(const float* __restrict__ xyz1, const float* __restrict__ xyz2,
              float* __restrict__ out) {
    extern __shared__ char smem[];
    const uint32_t su = smem_u32(smem);
    const int tid  = threadIdx.x;
    const int w    = tid >> 5, lane = tid & 31;
    const int wr   = w >> 1, wc = w & 1;
    const int lr   = lane >> 2, lc = lane & 3;
    const int b    = blockIdx.y;
    const int mt   = blockIdx.x;
    const int m0   = mt * BM;

    const float* X1 = xyz1 + (size_t)b * 3 * N1_;
    const float* X2 = xyz2 + (size_t)b * 3 * N2_;

    // Prologue: A image + B tiles 0,1 into bufs 0,1
    const float* gA = g_Asplit + (size_t)(b * MT + mt) * (GA * 8 * 128);
    for (int i = tid; i < ABYTES / 16; i += NTH) cpa16(su + i * 16, gA + i * 4);
    {
        const float* gB = g_Bsplit + (size_t)(b * NT) * (GB * 4 * 128);
        for (int i = tid; i < 2 * NCHB; i += NTH)
            cpa16(su + B0_OFF + i * 16, gB + i * 4);
    }
    CP_COMMIT();
    CP_WAIT0();
    __syncthreads();

    float bestV[4] = {-FLT_MAX, -FLT_MAX, -FLT_MAX, -FLT_MAX};
    int   bestI[4] = {0, 0, 0, 0};

    const char* aB = smem + (size_t)lane * 16;

    for (int it = 0; it < NT / 2; it++) {
        const int t0 = 2 * it, t1 = t0 + 1;
        const bool pf = (t0 + 2 < NT);
        const uint32_t pd0 = su + B0_OFF + ((t0 + 2) & 3) * BBYTES;
        const uint32_t pd1 = su + B0_OFF + ((t1 + 2) & 3) * BBYTES;
        const float* pg0 = g_Bsplit + (size_t)(b * NT + t0 + 2) * (GB * 4 * 128);
        const float* pg1 = g_Bsplit + (size_t)(b * NT + t1 + 2) * (GB * 4 * 128);

        // One tile-half: MMA over buffer, epilogue, with prefetch slots [ps, ps+5)
        #pragma unroll
        for (int half = 0; half < 2; half++) {
            const int t = half ? t1 : t0;
            const int ps = half * 5;
            const char* bB = smem + B0_OFF + (t & 3) * BBYTES + (size_t)lane * 16;

            float acc[2][4][4];
            #pragma unroll
            for (int f = 0; f < 2; f++)
                #pragma unroll
                for (int nf = 0; nf < 4; nf++)
                    #pragma unroll
                    for (int r = 0; r < 4; r++) acc[f][nf][r] = 0.f;

            #pragma unroll
            for (int g = 0; g < 4; g++) {
                if (pf) {   // spread 2-tile prefetch: chunk-set (ps+g)
                    int i = (ps + g) * NTH + tid;
                    if (i < 2 * NCHB) {
                        if (i < NCHB) cpa16(pd0 + i * 16, pg0 + i * 4);
                        else          cpa16(pd1 + (i - NCHB) * 16, pg1 + (i - NCHB) * 4);
                    }
                }
                uint4 aH0 = *(const uint4*)(aB + ((size_t)(g * 8       + wr * 2 + 0)) * 512);
                uint4 aH1 = *(const uint4*)(aB + ((size_t)(g * 8       + wr * 2 + 1)) * 512);
                uint4 aL0 = *(const uint4*)(aB + ((size_t)((4 + g) * 8 + wr * 2 + 0)) * 512);
                uint4 aL1 = *(const uint4*)(aB + ((size_t)((4 + g) * 8 + wr * 2 + 1)) * 512);
                uint4 bH0 = *(const uint4*)(bB + ((size_t)(g * 4       + wc * 2 + 0)) * 512);
                uint4 bH1 = *(const uint4*)(bB + ((size_t)(g * 4       + wc * 2 + 1)) * 512);
                uint4 bL0 = *(const uint4*)(bB + ((size_t)((4 + g) * 4 + wc * 2 + 0)) * 512);
                uint4 bL1 = *(const uint4*)(bB + ((size_t)((4 + g) * 4 + wc * 2 + 1)) * 512);
                // H.H
                MMA16(acc[0][0], aH0, bH0.x, bH0.y);
                MMA16(acc[0][1], aH0, bH0.z, bH0.w);
                MMA16(acc[0][2], aH0, bH1.x, bH1.y);
                MMA16(acc[0][3], aH0, bH1.z, bH1.w);
                MMA16(acc[1][0], aH1, bH0.x, bH0.y);
                MMA16(acc[1][1], aH1, bH0.z, bH0.w);
                MMA16(acc[1][2], aH1, bH1.x, bH1.y);
                MMA16(acc[1][3], aH1, bH1.z, bH1.w);
                // L.H
                MMA16(acc[0][0], aL0, bH0.x, bH0.y);
                MMA16(acc[0][1], aL0, bH0.z, bH0.w);
                MMA16(acc[0][2], aL0, bH1.x, bH1.y);
                MMA16(acc[0][3], aL0, bH1.z, bH1.w);
                MMA16(acc[1][0], aL1, bH0.x, bH0.y);
                MMA16(acc[1][1], aL1, bH0.z, bH0.w);
                MMA16(acc[1][2], aL1, bH1.x, bH1.y);
                MMA16(acc[1][3], aL1, bH1.z, bH1.w);
                // H.L
                MMA16(acc[0][0], aH0, bL0.x, bL0.y);
                MMA16(acc[0][1], aH0, bL0.z, bL0.w);
                MMA16(acc[0][2], aH0, bL1.x, bL1.y);
                MMA16(acc[0][3], aH0, bL1.z, bL1.w);
                MMA16(acc[1][0], aH1, bL0.x, bL0.y);
                MMA16(acc[1][1], aH1, bL0.z, bL0.w);
                MMA16(acc[1][2], aH1, bL1.x, bL1.y);
                MMA16(acc[1][3], aH1, bL1.z, bL1.w);
            }
            // xyz + sq group
            {
                if (pf) {
                    int i = (ps + 4) * NTH + tid;
                    if (i < 2 * NCHB) {
                        if (i < NCHB) cpa16(pd0 + i * 16, pg0 + i * 4);
                        else          cpa16(pd1 + (i - NCHB) * 16, pg1 + (i - NCHB) * 4);
                    }
                }
                uint4 a0 = *(const uint4*)(aB + ((size_t)(64 + wr * 2 + 0)) * 512);
                uint4 a1 = *(const uint4*)(aB + ((size_t)(64 + wr * 2 + 1)) * 512);
                uint4 b0 = *(const uint4*)(bB + ((size_t)(32 + wc * 2 + 0)) * 512);
                uint4 b1 = *(const uint4*)(bB + ((size_t)(32 + wc * 2 + 1)) * 512);
                MMA16(acc[0][0], a0, b0.x, b0.y);
                MMA16(acc[0][1], a0, b0.z, b0.w);
                MMA16(acc[0][2], a0, b1.x, b1.y);
                MMA16(acc[0][3], a0, b1.z, b1.w);
                MMA16(acc[1][0], a1, b0.x, b0.y);
                MMA16(acc[1][1], a1, b0.z, b0.w);
                MMA16(acc[1][2], a1, b1.x, b1.y);
                MMA16(acc[1][3], a1, b1.z, b1.w);
            }

            // Epilogue: acc = dot - sq/2; per-row max tree + rare index recovery
            #pragma unroll
            for (int f = 0; f < 2; f++)
                #pragma unroll
                for (int h = 0; h < 2; h++) {
                    const int bi = f * 2 + h;
                    float m01 = fmaxf(acc[f][0][h * 2], acc[f][0][h * 2 + 1]);
                    float m23 = fmaxf(acc[f][1][h * 2], acc[f][1][h * 2 + 1]);
                    float m45 = fmaxf(acc[f][2][h * 2], acc[f][2][h * 2 + 1]);
                    float m67 = fmaxf(acc[f][3][h * 2], acc[f][3][h * 2 + 1]);
                    float m = fmaxf(fmaxf(m01, m23), fmaxf(m45, m67));
                    if (m > bestV[bi]) {
                        bestV[bi] = m;
                        int jj = 0;
                        #pragma unroll
                        for (int nf = 3; nf >= 0; nf--)
                            #pragma unroll
                            for (int c = 1; c >= 0; c--)
                                if (acc[f][nf][h * 2 + c] == m)
                                    jj = t * BN + wc * 32 + nf * 8 + 2 * lc + c;
                        bestI[bi] = jj;   // descending scan => smallest j wins
                    }
                }
        }

        if (pf) CP_COMMIT();
        CP_WAIT0();
        __syncthreads();
    }

    // Lane reduction across lc
    #pragma unroll
    for (int off = 1; off <= 2; off <<= 1) {
        #pragma unroll
        for (int r = 0; r < 4; r++) {
            float ov = __shfl_xor_sync(0xffffffff, bestV[r], off);
            int   oi = __shfl_xor_sync(0xffffffff, bestI[r], off);
            if (ov > bestV[r] || (ov == bestV[r] && oi < bestI[r])) {
                bestV[r] = ov; bestI[r] = oi;
            }
        }
    }
    __syncthreads();
    float* sv = (float*)smem;
    int*   si = (int*)(smem + 128 * 2 * 4);
    if (lc == 0) {
        #pragma unroll
        for (int r = 0; r < 4; r++) {
            int row = wr * 32 + (r >> 1) * 16 + lr + (r & 1) * 8;
            sv[row * 2 + wc] = bestV[r];
            si[row * 2 + wc] = bestI[r];
        }
    }
    __syncthreads();

    if (tid < BM) {
        float v0 = sv[tid * 2], v1 = sv[tid * 2 + 1];
        int   i0 = si[tid * 2], i1 = si[tid * 2 + 1];
        int   bi = (v1 > v0 || (v1 == v0 && i1 < i0)) ? i1 : i0;
        int   gi = m0 + tid;
        out[b * N1_ + gi]        = (float)gi;
        out[(B_ + b) * N1_ + gi] = (float)bi;
        float* dir = out + 2 * B_ * N1_;
        #pragma unroll
        for (int d = 0; d < 3; d++)
            dir[((size_t)b * 3 + d) * N1_ + gi] =
                X2[(size_t)d * N2_ + bi] - X1[(size_t)d * N1_ + gi];
    }
}

// ---------------------------------------------------------------------------
extern "C" void kernel_launch(void* const* d_in, const int* in_sizes, int n_in,
                              void* d_out, int out_size) {
    const float* xyz1    = (const float*)d_in[0];
    const float* xyz2    = (const float*)d_in[1];
    const float* points1 = (const float*)d_in[2];
    const float* points2 = (const float*)d_in[3];
    float* out = (float*)d_out;

    sq2_kernel<<<(B_ * N2_ + 255) / 256, 256>>>(xyz2, points2);
    {
        int warpsA = B_ * MT * GA * 8;
        prepA_kernel<<<(warpsA * 32 + NTH - 1) / NTH, NTH>>>(xyz1, points1);
        int warpsB = B_ * NT * GB * 4;
        prepB_kernel<<<(warpsB * 32 + NTH - 1) / NTH, NTH>>>(xyz2, points2);
    }

    cudaFuncSetAttribute(nn_mma_kernel,
                         cudaFuncAttributeMaxDynamicSharedMemorySize,
                         SMEM_TOTAL);
    dim3 grid(MT, B_);
    nn_mma_kernel<<<grid, NTH, SMEM_TOTAL>>>(xyz1, xyz2, out);
}

// round 10
// speedup vs baseline: 7.1981x; 1.0066x over previous
#include <cuda_runtime.h>
#include <cuda_fp16.h>
#include <float.h>
#include <stdint.h>

// Problem constants
#define B_   2
#define D_   64
#define N1_  16384
#define N2_  16384

#define BM 128
#define BN 128
#define NT (N2_/BN)      // 128
#define MT (N1_/BM)      // 128
#define GA 9             // A k-groups: 4 H + 4 L + 1 xyz/sq
#define GB 9             // B k-groups: 4 H + 4 L + 1 xyz/sq
#define NTH 256

// SMEM layout (bytes): A image + 2-deep B ring (BN=128 tiles)
#define ABYTES (GA*8*512)             // 36864
#define BBYTES (GB*8*512)             // 36864
#define B0_OFF ABYTES
#define SMEM_TOTAL (ABYTES + 2*BBYTES)  // 110592 -> 2 CTAs/SM
#define NCHB (BBYTES/16)              // 2304 chunks per B tile

// Scratch
__device__ float g_sq2[B_ * N2_];
__device__ float g_Asplit[(size_t)B_ * MT * GA * 8 * 128];
__device__ float g_Bsplit[(size_t)B_ * NT * GB * 8 * 128];

// ---------------------------------------------------------------------------
__device__ __forceinline__ uint16_t hi_h(float x) {
    return __half_as_ushort(__float2half_rn(x));
}
__device__ __forceinline__ uint16_t lo_h(float x) {
    __half h = __float2half_rn(x);
    return __half_as_ushort(__float2half_rn(x - __half2float(h)));
}
__device__ __forceinline__ uint16_t slotA(const float* P1, const float* X1,
                                          int ga, int sl, int m) {
    if (ga < 4)  return hi_h(P1[(size_t)(ga * 16 + sl) * N1_ + m]);
    if (ga < 8)  return lo_h(P1[(size_t)((ga - 4) * 16 + sl) * N1_ + m]);
    if (sl < 3)  return hi_h(X1[(size_t)sl * N1_ + m]);
    if (sl < 6)  return lo_h(X1[(size_t)(sl - 3) * N1_ + m]);
    if (sl < 9)  return hi_h(X1[(size_t)(sl - 6) * N1_ + m]);
    if (sl < 11) return 0x3C00;  // 1.0h (sq carriers)
    return 0;
}
__device__ __forceinline__ uint16_t slotB(const float* P2, const float* X2,
                                          const float* SQ, int gb, int sl, int n) {
    if (gb < 4)  return hi_h(P2[(size_t)(gb * 16 + sl) * N2_ + n]);
    if (gb < 8)  return lo_h(P2[(size_t)((gb - 4) * 16 + sl) * N2_ + n]);
    if (sl < 3)  return hi_h(X2[(size_t)sl * N2_ + n]);
    if (sl < 6)  return hi_h(X2[(size_t)(sl - 3) * N2_ + n]);
    if (sl < 9)  return lo_h(X2[(size_t)(sl - 6) * N2_ + n]);
    float v = -0.5f * SQ[n];
    if (sl == 9)  return hi_h(v);
    if (sl == 10) return lo_h(v);
    return 0;
}
__device__ __forceinline__ uint32_t packh(uint16_t a, uint16_t b) {
    return (uint32_t)a | ((uint32_t)b << 16);
}

#define MMA16(C, A, b0v, b1v)                                             \
  asm volatile("mma.sync.aligned.m16n8k16.row.col.f32.f16.f16.f32 "       \
    "{%0,%1,%2,%3}, {%4,%5,%6,%7}, {%8,%9}, {%0,%1,%2,%3};"               \
    : "+f"((C)[0]), "+f"((C)[1]), "+f"((C)[2]), "+f"((C)[3])              \
    : "r"((A).x), "r"((A).y), "r"((A).z), "r"((A).w), "r"(b0v), "r"(b1v))

__device__ __forceinline__ uint32_t smem_u32(const void* p) {
    uint32_t a;
    asm("{ .reg .u64 t; cvta.to.shared.u64 t, %1; cvt.u32.u64 %0, t; }" : "=r"(a) : "l"(p));
    return a;
}
__device__ __forceinline__ void cpa16(uint32_t s, const void* g) {
    asm volatile("cp.async.cg.shared.global [%0], [%1], 16;" :: "r"(s), "l"(g) : "memory");
}
#define CP_COMMIT() asm volatile("cp.async.commit_group;" ::: "memory")
#define CP_WAIT0()  asm volatile("cp.async.wait_group 0;" ::: "memory")

// ---------------------------------------------------------------------------
__global__ void sq2_kernel(const float* __restrict__ xyz2,
                           const float* __restrict__ points2) {
    int idx = blockIdx.x * blockDim.x + threadIdx.x;
    if (idx >= B_ * N2_) return;
    int b = idx / N2_, j = idx % N2_;
    const float* p = points2 + (size_t)b * D_ * N2_ + j;
    float s = 0.f;
    #pragma unroll
    for (int d = 0; d < D_; d++) { float v = p[(size_t)d * N2_]; s += v * v; }
    const float* x = xyz2 + (size_t)b * 3 * N2_ + j;
    #pragma unroll
    for (int d = 0; d < 3; d++) { float v = x[(size_t)d * N2_]; s += v * v; }
    g_sq2[idx] = s;
}

__global__ void prepA_kernel(const float* __restrict__ xyz1,
                             const float* __restrict__ points1) {
    int gw   = (blockIdx.x * blockDim.x + threadIdx.x) >> 5;
    int lane = threadIdx.x & 31;
    if (gw >= B_ * MT * GA * 8) return;
    int ab = gw % (GA * 8); int rem = gw / (GA * 8);
    int mt = rem % MT;      int b   = rem / MT;
    const float* P1 = points1 + (size_t)b * D_ * N1_;
    const float* X1 = xyz1    + (size_t)b * 3  * N1_;
    int ga = ab >> 3, fA = ab & 7;
    int lr = lane >> 2, lc = lane & 3;
    int m1 = mt * BM + fA * 16 + lr, m2 = m1 + 8;
    int s0 = 2 * lc;
    uint4 v;
    v.x = packh(slotA(P1, X1, ga, s0,     m1), slotA(P1, X1, ga, s0 + 1, m1));
    v.y = packh(slotA(P1, X1, ga, s0,     m2), slotA(P1, X1, ga, s0 + 1, m2));
    v.z = packh(slotA(P1, X1, ga, s0 + 8, m1), slotA(P1, X1, ga, s0 + 9, m1));
    v.w = packh(slotA(P1, X1, ga, s0 + 8, m2), slotA(P1, X1, ga, s0 + 9, m2));
    ((uint4*)g_Asplit)[(size_t)gw * 32 + lane] = v;
}

__global__ void prepB_kernel(const float* __restrict__ xyz2,
                             const float* __restrict__ points2) {
    int gw   = (blockIdx.x * blockDim.x + threadIdx.x) >> 5;
    int lane = threadIdx.x & 31;
    if (gw >= B_ * NT * GB * 8) return;
    int sb = gw % (GB * 8); int rem = gw / (GB * 8);
    int nt = rem % NT;      int b   = rem / NT;
    const float* P2 = points2 + (size_t)b * D_ * N2_;
    const float* X2 = xyz2    + (size_t)b * 3  * N2_;
    const float* SQ = g_sq2   + (size_t)b * N2_;
    int gb = sb >> 3, q = sb & 7;
    int lr = lane >> 2, lc = lane & 3;
    int n1 = nt * BN + q * 16 + lr, n2 = n1 + 8;
    int s0 = 2 * lc;
    uint4 v;
    v.x = packh(slotB(P2, X2, SQ, gb, s0,     n1), slotB(P2, X2, SQ, gb, s0 + 1, n1));
    v.y = packh(slotB(P2, X2, SQ, gb, s0 + 8, n1), slotB(P2, X2, SQ, gb, s0 + 9, n1));
    v.z = packh(slotB(P2, X2, SQ, gb, s0,     n2), slotB(P2, X2, SQ, gb, s0 + 1, n2));
    v.w = packh(slotB(P2, X2, SQ, gb, s0 + 8, n2), slotB(P2, X2, SQ, gb, s0 + 9, n2));
    ((uint4*)g_Bsplit)[(size_t)gw * 32 + lane] = v;
}

// ---------------------------------------------------------------------------
// Main: warp tile 32m x 64n (warp grid 4x2, CTA 128x128), double-buffered B.
// ---------------------------------------------------------------------------
__global__ void __launch_bounds__(NTH, 2)
nn_mma_kernel(const float* __restrict__ xyz1, const float* __restrict__ xyz2,
              float* __restrict__ out) {
    extern __shared__ char smem[];
    const uint32_t su = smem_u32(smem);
    const int tid  = threadIdx.x;
    const int w    = tid >> 5, lane = tid & 31;
    const int wr   = w >> 1, wc = w & 1;       // 4m x 2n warp grid
    const int lr   = lane >> 2, lc = lane & 3;
    const int b    = blockIdx.y;
    const int mt   = blockIdx.x;
    const int m0   = mt * BM;

    const float* X1 = xyz1 + (size_t)b * 3 * N1_;
    const float* X2 = xyz2 + (size_t)b * 3 * N2_;

    // Prologue: A image + B tile 0
    const float* gA = g_Asplit + (size_t)(b * MT + mt) * (GA * 8 * 128);
    for (int i = tid; i < ABYTES / 16; i += NTH) cpa16(su + i * 16, gA + i * 4);
    {
        const float* gB = g_Bsplit + (size_t)(b * NT) * (GB * 8 * 128);
        for (int i = tid; i < NCHB; i += NTH) cpa16(su + B0_OFF + i * 16, gB + i * 4);
    }
    CP_COMMIT();
    CP_WAIT0();
    __syncthreads();

    float bestV[4] = {-FLT_MAX, -FLT_MAX, -FLT_MAX, -FLT_MAX};
    int   bestI[4] = {0, 0, 0, 0};

    const char* aB = smem + (size_t)lane * 16;

    for (int t = 0; t < NT; t++) {
        const int cur = t & 1;
        const char* bB = smem + B0_OFF + cur * BBYTES + (size_t)lane * 16;
        const uint32_t bufN = su + B0_OFF + (cur ^ 1) * BBYTES;
        const float* gB = g_Bsplit + (size_t)(b * NT + t + 1) * (GB * 8 * 128);
        const bool pf = (t + 1 < NT);

        float acc[2][8][4];
        #pragma unroll
        for (int f = 0; f < 2; f++)
            #pragma unroll
            for (int nf = 0; nf < 8; nf++)
                #pragma unroll
                for (int r = 0; r < 4; r++) acc[f][nf][r] = 0.f;

        // 4 point-dim groups with 3-term register reuse
        #pragma unroll
        for (int g = 0; g < 4; g++) {
            if (pf) {   // spread prefetch: 2 chunk-sets per group
                int i0 = (g * 2) * NTH + tid;
                if (i0 < NCHB) cpa16(bufN + i0 * 16, gB + i0 * 4);
                int i1 = (g * 2 + 1) * NTH + tid;
                if (i1 < NCHB) cpa16(bufN + i1 * 16, gB + i1 * 4);
            }
            // Phase 1: H.H
            uint4 aH0 = *(const uint4*)(aB + ((size_t)(g * 8 + wr * 2 + 0)) * 512);
            uint4 aH1 = *(const uint4*)(aB + ((size_t)(g * 8 + wr * 2 + 1)) * 512);
            uint4 bH0 = *(const uint4*)(bB + ((size_t)(g * 8 + wc * 4 + 0)) * 512);
            uint4 bH1 = *(const uint4*)(bB + ((size_t)(g * 8 + wc * 4 + 1)) * 512);
            uint4 bH2 = *(const uint4*)(bB + ((size_t)(g * 8 + wc * 4 + 2)) * 512);
            uint4 bH3 = *(const uint4*)(bB + ((size_t)(g * 8 + wc * 4 + 3)) * 512);
            MMA16(acc[0][0], aH0, bH0.x, bH0.y);
            MMA16(acc[0][1], aH0, bH0.z, bH0.w);
            MMA16(acc[0][2], aH0, bH1.x, bH1.y);
            MMA16(acc[0][3], aH0, bH1.z, bH1.w);
            MMA16(acc[0][4], aH0, bH2.x, bH2.y);
            MMA16(acc[0][5], aH0, bH2.z, bH2.w);
            MMA16(acc[0][6], aH0, bH3.x, bH3.y);
            MMA16(acc[0][7], aH0, bH3.z, bH3.w);
            MMA16(acc[1][0], aH1, bH0.x, bH0.y);
            MMA16(acc[1][1], aH1, bH0.z, bH0.w);
            MMA16(acc[1][2], aH1, bH1.x, bH1.y);
            MMA16(acc[1][3], aH1, bH1.z, bH1.w);
            MMA16(acc[1][4], aH1, bH2.x, bH2.y);
            MMA16(acc[1][5], aH1, bH2.z, bH2.w);
            MMA16(acc[1][6], aH1, bH3.x, bH3.y);
            MMA16(acc[1][7], aH1, bH3.z, bH3.w);
            // Phase 2: L.H (loads aL; bH still live)
            uint4 aL0 = *(const uint4*)(aB + ((size_t)((4 + g) * 8 + wr * 2 + 0)) * 512);
            uint4 aL1 = *(const uint4*)(aB + ((size_t)((4 + g) * 8 + wr * 2 + 1)) * 512);
            MMA16(acc[0][0], aL0, bH0.x, bH0.y);
            MMA16(acc[0][1], aL0, bH0.z, bH0.w);
            MMA16(acc[0][2], aL0, bH1.x, bH1.y);
            MMA16(acc[0][3], aL0, bH1.z, bH1.w);
            MMA16(acc[0][4], aL0, bH2.x, bH2.y);
            MMA16(acc[0][5], aL0, bH2.z, bH2.w);
            MMA16(acc[0][6], aL0, bH3.x, bH3.y);
            MMA16(acc[0][7], aL0, bH3.z, bH3.w);
            MMA16(acc[1][0], aL1, bH0.x, bH0.y);
            MMA16(acc[1][1], aL1, bH0.z, bH0.w);
            MMA16(acc[1][2], aL1, bH1.x, bH1.y);
            MMA16(acc[1][3], aL1, bH1.z, bH1.w);
            MMA16(acc[1][4], aL1, bH2.x, bH2.y);
            MMA16(acc[1][5], aL1, bH2.z, bH2.w);
            MMA16(acc[1][6], aL1, bH3.x, bH3.y);
            MMA16(acc[1][7], aL1, bH3.z, bH3.w);
            // Phase 3: H.L (bH regs dead; load bL)
            uint4 bL0 = *(const uint4*)(bB + ((size_t)((4 + g) * 8 + wc * 4 + 0)) * 512);
            uint4 bL1 = *(const uint4*)(bB + ((size_t)((4 + g) * 8 + wc * 4 + 1)) * 512);
            uint4 bL2 = *(const uint4*)(bB + ((size_t)((4 + g) * 8 + wc * 4 + 2)) * 512);
            uint4 bL3 = *(const uint4*)(bB + ((size_t)((4 + g) * 8 + wc * 4 + 3)) * 512);
            MMA16(acc[0][0], aH0, bL0.x, bL0.y);
            MMA16(acc[0][1], aH0, bL0.z, bL0.w);
            MMA16(acc[0][2], aH0, bL1.x, bL1.y);
            MMA16(acc[0][3], aH0, bL1.z, bL1.w);
            MMA16(acc[0][4], aH0, bL2.x, bL2.y);
            MMA16(acc[0][5], aH0, bL2.z, bL2.w);
            MMA16(acc[0][6], aH0, bL3.x, bL3.y);
            MMA16(acc[0][7], aH0, bL3.z, bL3.w);
            MMA16(acc[1][0], aH1, bL0.x, bL0.y);
            MMA16(acc[1][1], aH1, bL0.z, bL0.w);
            MMA16(acc[1][2], aH1, bL1.x, bL1.y);
            MMA16(acc[1][3], aH1, bL1.z, bL1.w);
            MMA16(acc[1][4], aH1, bL2.x, bL2.y);
            MMA16(acc[1][5], aH1, bL2.z, bL2.w);
            MMA16(acc[1][6], aH1, bL3.x, bL3.y);
            MMA16(acc[1][7], aH1, bL3.z, bL3.w);
        }
        // xyz + sq group
        {
            if (pf) {
                int i0 = 8 * NTH + tid;
                if (i0 < NCHB) cpa16(bufN + i0 * 16, gB + i0 * 4);
                int i1 = 9 * NTH + tid;
                if (i1 < NCHB) cpa16(bufN + i1 * 16, gB + i1 * 4);
            }
            uint4 a0 = *(const uint4*)(aB + ((size_t)(64 + wr * 2 + 0)) * 512);
            uint4 a1 = *(const uint4*)(aB + ((size_t)(64 + wr * 2 + 1)) * 512);
            uint4 b0 = *(const uint4*)(bB + ((size_t)(64 + wc * 4 + 0)) * 512);
            uint4 b1 = *(const uint4*)(bB + ((size_t)(64 + wc * 4 + 1)) * 512);
            uint4 b2 = *(const uint4*)(bB + ((size_t)(64 + wc * 4 + 2)) * 512);
            uint4 b3 = *(const uint4*)(bB + ((size_t)(64 + wc * 4 + 3)) * 512);
            MMA16(acc[0][0], a0, b0.x, b0.y);
            MMA16(acc[0][1], a0, b0.z, b0.w);
            MMA16(acc[0][2], a0, b1.x, b1.y);
            MMA16(acc[0][3], a0, b1.z, b1.w);
            MMA16(acc[0][4], a0, b2.x, b2.y);
            MMA16(acc[0][5], a0, b2.z, b2.w);
            MMA16(acc[0][6], a0, b3.x, b3.y);
            MMA16(acc[0][7], a0, b3.z, b3.w);
            MMA16(acc[1][0], a1, b0.x, b0.y);
            MMA16(acc[1][1], a1, b0.z, b0.w);
            MMA16(acc[1][2], a1, b1.x, b1.y);
            MMA16(acc[1][3], a1, b1.z, b1.w);
            MMA16(acc[1][4], a1, b2.x, b2.y);
            MMA16(acc[1][5], a1, b2.z, b2.w);
            MMA16(acc[1][6], a1, b3.x, b3.y);
            MMA16(acc[1][7], a1, b3.z, b3.w);
        }
        if (pf) CP_COMMIT();

        // Epilogue: per-row max tree over 16 values + rare index recovery
        #pragma unroll
        for (int f = 0; f < 2; f++)
            #pragma unroll
            for (int h = 0; h < 2; h++) {
                const int bi = f * 2 + h;
                float m = acc[f][0][h * 2];
                #pragma unroll
                for (int nf = 0; nf < 8; nf++) {
                    m = fmaxf(m, acc[f][nf][h * 2]);
                    m = fmaxf(m, acc[f][nf][h * 2 + 1]);
                }
                if (m > bestV[bi]) {
                    bestV[bi] = m;
                    int jj = 0;
                    #pragma unroll
                    for (int nf = 7; nf >= 0; nf--)
                        #pragma unroll
                        for (int c = 1; c >= 0; c--)
                            if (acc[f][nf][h * 2 + c] == m)
                                jj = t * BN + wc * 64 + nf * 8 + 2 * lc + c;
                    bestI[bi] = jj;   // descending scan => smallest j wins
                }
            }

        CP_WAIT0();
        __syncthreads();
    }

    // Lane reduction across lc
    #pragma unroll
    for (int off = 1; off <= 2; off <<= 1) {
        #pragma unroll
        for (int r = 0; r < 4; r++) {
            float ov = __shfl_xor_sync(0xffffffff, bestV[r], off);
            int   oi = __shfl_xor_sync(0xffffffff, bestI[r], off);
            if (ov > bestV[r] || (ov == bestV[r] && oi < bestI[r])) {
                bestV[r] = ov; bestI[r] = oi;
            }
        }
    }
    __syncthreads();
    float* sv = (float*)smem;
    int*   si = (int*)(smem + 128 * 2 * 4);
    if (lc == 0) {
        #pragma unroll
        for (int r = 0; r < 4; r++) {
            int row = wr * 32 + (r >> 1) * 16 + lr + (r & 1) * 8;
            sv[row * 2 + wc] = bestV[r];
            si[row * 2 + wc] = bestI[r];
        }
    }
    __syncthreads();

    if (tid < BM) {
        float v0 = sv[tid * 2], v1 = sv[tid * 2 + 1];
        int   i0 = si[tid * 2], i1 = si[tid * 2 + 1];
        int   bi = (v1 > v0 || (v1 == v0 && i1 < i0)) ? i1 : i0;
        int   gi = m0 + tid;
        out[b * N1_ + gi]        = (float)gi;
        out[(B_ + b) * N1_ + gi] = (float)bi;
        float* dir = out + 2 * B_ * N1_;
        #pragma unroll
        for (int d = 0; d < 3; d++)
            dir[((size_t)b * 3 + d) * N1_ + gi] =
                X2[(size_t)d * N2_ + bi] - X1[(size_t)d * N1_ + gi];
    }
}

// ---------------------------------------------------------------------------
extern "C" void kernel_launch(void* const* d_in, const int* in_sizes, int n_in,
                              void* d_out, int out_size) {
    const float* xyz1    = (const float*)d_in[0];
    const float* xyz2    = (const float*)d_in[1];
    const float* points1 = (const float*)d_in[2];
    const float* points2 = (const float*)d_in[3];
    float* out = (float*)d_out;

    sq2_kernel<<<(B_ * N2_ + 255) / 256, 256>>>(xyz2, points2);
    {
        int warpsA = B_ * MT * GA * 8;
        prepA_kernel<<<(warpsA * 32 + NTH - 1) / NTH, NTH>>>(xyz1, points1);
        int warpsB = B_ * NT * GB * 8;
        prepB_kernel<<<(warpsB * 32 + NTH - 1) / NTH, NTH>>>(xyz2, points2);
    }

    cudaFuncSetAttribute(nn_mma_kernel,
                         cudaFuncAttributeMaxDynamicSharedMemorySize,
                         SMEM_TOTAL);
    dim3 grid(MT, B_);
    nn_mma_kernel<<<grid, NTH, SMEM_TOTAL>>>(xyz1, xyz2, out);
}